// round 3
// baseline (speedup 1.0000x reference)
#include <cuda_runtime.h>

// Problem constants
#define Nn 64
#define Cc 256
#define Ss 64
#define Pp 16
#define Kk 4
#define Hh 4
#define Dd 64
#define Bb (Nn*Pp)      // 1024
#define MR (Bb*Ss)      // 65536 rows for the big GEMMs

// Scratch (device-static; no allocations allowed)
__device__ float g_x2 [MR*Cc];   // x2, later x_attn (residual added in place)
__device__ float g_q  [MR*Cc];   // Q, later attention output (in place)
__device__ float g_k  [MR*Cc];
__device__ float g_v  [MR*Cc];
__device__ float g_clus[Pp*Nn*Kk*Cc];
__device__ int   g_hard[Pp*Nn*Ss];

// ---------------------------------------------------------------------------
// transpose: x (n,c,s,p) -> x2 (n*p, s, c)
// ---------------------------------------------------------------------------
__global__ void transpose_kernel(const float* __restrict__ x){
    __shared__ float tile[32][129];
    int n  = blockIdx.z;
    int c0 = blockIdx.x * 32;
    int sp0= blockIdx.y * 128;
    int t  = threadIdx.x;
    #pragma unroll
    for (int it = 0; it < 16; ++it){
        int idx = it*256 + t;
        int cl = idx >> 7, spl = idx & 127;
        tile[cl][spl] = x[(n*Cc + c0 + cl)*1024 + sp0 + spl];
    }
    __syncthreads();
    #pragma unroll
    for (int it = 0; it < 4; ++it){
        int spl = it*32 + (t >> 3);
        int cl  = (t & 7) * 4;
        int sp  = sp0 + spl;
        int s = sp >> 4, p = sp & 15;
        float4 v = make_float4(tile[cl][spl], tile[cl+1][spl],
                               tile[cl+2][spl], tile[cl+3][spl]);
        *(float4*)&g_x2[((n*Pp + p)*Ss + s)*Cc + c0 + cl] = v;
    }
}

// ---------------------------------------------------------------------------
// clustering: instance-norm over s, cosine sim vs normalized prototypes,
// hard argmax over k. One block per (p,n).
// ---------------------------------------------------------------------------
__global__ void cluster_kernel(const float* __restrict__ x,
                               const float* __restrict__ protos){
    __shared__ float mu[256], rs[256];
    __shared__ float pr[4][256];
    __shared__ float pn[4];
    int bx = blockIdx.x;
    int p = bx >> 6, n = bx & 63;
    int t = threadIdx.x;

    for (int i = t; i < 1024; i += 256) pr[i>>8][i&255] = protos[p*1024 + i];
    __syncthreads();
    if (t < 4){
        float s = 0.f;
        for (int c = 0; c < 256; ++c){ float v = pr[t][c]; s += v*v; }
        pn[t] = rsqrtf(s);
    }
    __syncthreads();
    for (int i = t; i < 1024; i += 256) pr[i>>8][i&255] *= pn[i>>8];

    {   // mean / biased var over s for channel c = t
        int c = t;
        const float* xp = x + (n*256 + c)*1024 + p;
        float s1 = 0.f, s2 = 0.f;
        for (int s = 0; s < 64; ++s){ float v = xp[s*16]; s1 += v; s2 += v*v; }
        float m = s1 * (1.f/64.f);
        float var = s2 * (1.f/64.f) - m*m;
        mu[c] = m; rs[c] = rsqrtf(var + 1e-5f);
    }
    __syncthreads();

    // per-s: L2 norm over c + 4 prototype dots; 4 lanes per s
    int s = t >> 2, q4 = t & 3;
    const float* xs = x + (n*256)*1024 + s*16 + p;
    float nr = 0.f, d0=0.f, d1=0.f, d2=0.f, d3=0.f;
    for (int cc = 0; cc < 64; ++cc){
        int c = cc*4 + q4;
        float v = (xs[c*1024] - mu[c]) * rs[c];
        nr += v*v;
        d0 += v*pr[0][c]; d1 += v*pr[1][c];
        d2 += v*pr[2][c]; d3 += v*pr[3][c];
    }
    #pragma unroll
    for (int off = 1; off < 4; off <<= 1){
        nr += __shfl_xor_sync(0xffffffffu, nr, off);
        d0 += __shfl_xor_sync(0xffffffffu, d0, off);
        d1 += __shfl_xor_sync(0xffffffffu, d1, off);
        d2 += __shfl_xor_sync(0xffffffffu, d2, off);
        d3 += __shfl_xor_sync(0xffffffffu, d3, off);
    }
    if (q4 == 0){
        float inv = rsqrtf(nr);
        float s0 = d0*inv, s1v = d1*inv, s2v = d2*inv, s3v = d3*inv;
        int best = 0; float bv = s0;
        if (s1v > bv){ bv = s1v; best = 1; }
        if (s2v > bv){ bv = s2v; best = 2; }
        if (s3v > bv){ bv = s3v; best = 3; }
        g_hard[(p*64 + n)*64 + s] = best;
    }
}

// mode over parts -> cluster_indices (n,s), first-max tie-break, as float
__global__ void mode_kernel(float* __restrict__ outTail){
    int t = blockIdx.x*256 + threadIdx.x;       // 4096 = n*s
    int n = t >> 6, s = t & 63;
    int cnt[4] = {0,0,0,0};
    #pragma unroll
    for (int p = 0; p < 16; ++p) cnt[g_hard[(p*64+n)*64 + s]]++;
    int best = 0, bv = cnt[0];
    if (cnt[1] > bv){ bv = cnt[1]; best = 1; }
    if (cnt[2] > bv){ bv = cnt[2]; best = 2; }
    if (cnt[3] > bv){ bv = cnt[3]; best = 3; }
    outTail[t] = (float)best;
}

// ---------------------------------------------------------------------------
// generic SGEMM: C = A(MxK) * B(Kx256) [+bias] [+residual g_x2]
// BM=128, BN=64, BK=16, 256 threads, 8x4 per thread.
// M bound checks REQUIRED: the final FC launch has M=64 < BM=128; without the
// guards its tile rows 64..127 clobber the cluster_indices tail of d_out.
// ---------------------------------------------------------------------------
__device__ __forceinline__ float* selbuf(int sel, float* ext){
    switch (sel){
        case 0: return g_x2;
        case 1: return g_q;
        case 2: return g_k;
        case 3: return g_v;
        case 4: return g_clus;
        default: return ext;
    }
}

__global__ void sgemm_kernel(int aSel, const float* __restrict__ Bm,
                             const float* __restrict__ bias, int useRes,
                             int cSel, float* extC, int cstride,
                             int M, int K, int lda, int perp)
{
    __shared__ float As[16][132];
    __shared__ float Bs[16][64];
    const float* A = selbuf(aSel, nullptr);
    float* C = selbuf(cSel, extC);
    const float* Bp = Bm;
    if (perp){
        int z = blockIdx.z;
        A  += z * 64 * 1024;
        Bp += z * 1024 * 256;
        C  += z;
    }
    int mbase = blockIdx.x * 128;
    int nbase = blockIdx.y * 64;
    int t = threadIdx.x;
    int tx = t & 15, ty = t >> 4;

    float acc[8][4];
    #pragma unroll
    for (int i=0;i<8;i++)
        #pragma unroll
        for (int j=0;j<4;j++) acc[i][j]=0.f;

    int arow = t >> 1;
    int ak   = (t & 1) * 8;
    int brow = t >> 4;
    int bc   = (t & 15) * 4;

    int ktiles = K >> 4;
    for (int kt = 0; kt < ktiles; ++kt){
        float4 a0, a1;
        if (mbase + arow < M){
            const float* ap = A + (mbase + arow)*lda + kt*16 + ak;
            a0 = *(const float4*)ap;
            a1 = *(const float4*)(ap + 4);
        } else {
            a0 = make_float4(0.f,0.f,0.f,0.f); a1 = a0;
        }
        As[ak+0][arow]=a0.x; As[ak+1][arow]=a0.y; As[ak+2][arow]=a0.z; As[ak+3][arow]=a0.w;
        As[ak+4][arow]=a1.x; As[ak+5][arow]=a1.y; As[ak+6][arow]=a1.z; As[ak+7][arow]=a1.w;
        *(float4*)&Bs[brow][bc] = *(const float4*)&Bp[(kt*16 + brow)*256 + nbase + bc];
        __syncthreads();
        #pragma unroll
        for (int k = 0; k < 16; ++k){
            float4 a0v = *(const float4*)&As[k][ty*8];
            float4 a1v = *(const float4*)&As[k][ty*8+4];
            float4 bv  = *(const float4*)&Bs[k][tx*4];
            float am[8] = {a0v.x,a0v.y,a0v.z,a0v.w,a1v.x,a1v.y,a1v.z,a1v.w};
            float bn[4] = {bv.x,bv.y,bv.z,bv.w};
            #pragma unroll
            for (int i=0;i<8;i++)
                #pragma unroll
                for (int j=0;j<4;j++)
                    acc[i][j] += am[i]*bn[j];
        }
        __syncthreads();
    }
    #pragma unroll
    for (int i=0;i<8;i++){
        int row = mbase + ty*8 + i;
        if (row >= M) continue;
        #pragma unroll
        for (int j=0;j<4;j++){
            int col = nbase + tx*4 + j;
            float v = acc[i][j];
            if (bias)   v += bias[col];
            if (useRes) v += g_x2[row*256 + col];
            C[(row*256 + col)*cstride] = v;
        }
    }
}

// ---------------------------------------------------------------------------
// causal attention per (b,h): S=64, D=64.
// ---------------------------------------------------------------------------
__global__ void attn_kernel(){
    __shared__ float smA[64*68];   // Q^T, then probs
    __shared__ float smB[64*68];   // K^T, then V
    int h = blockIdx.x, b = blockIdx.y;
    int t = threadIdx.x;
    const float* qb = g_q + (b*64)*256 + h*64;
    const float* kb = g_k + (b*64)*256 + h*64;
    const float* vb = g_v + (b*64)*256 + h*64;

    #pragma unroll
    for (int it = 0; it < 16; ++it){
        int idx = it*256 + t;
        int s = idx >> 6, d = idx & 63;
        smA[d*68 + s] = qb[s*256 + d];
        smB[d*68 + s] = kb[s*256 + d];
    }
    __syncthreads();

    int ib = t >> 4, jb = t & 15;      // 16x16 thread grid, 4x4 tiles
    float acc[4][4];
    #pragma unroll
    for (int r=0;r<4;r++)
        #pragma unroll
        for (int c=0;c<4;c++) acc[r][c]=0.f;

    for (int d = 0; d < 64; ++d){
        float4 qa = *(const float4*)&smA[d*68 + ib*4];
        float4 ka = *(const float4*)&smB[d*68 + jb*4];
        float qv[4] = {qa.x,qa.y,qa.z,qa.w};
        float kv[4] = {ka.x,ka.y,ka.z,ka.w};
        #pragma unroll
        for (int r=0;r<4;r++)
            #pragma unroll
            for (int c=0;c<4;c++)
                acc[r][c] += qv[r]*kv[c];
    }

    // causal softmax, row reduce across the 16 jb lanes (same warp half)
    #pragma unroll
    for (int r=0;r<4;r++){
        int i = ib*4 + r;
        float m = -1e30f;
        #pragma unroll
        for (int c=0;c<4;c++){
            int j = jb*4 + c;
            float sc = (j <= i) ? acc[r][c]*0.125f : -1e30f;
            acc[r][c] = sc;
            m = fmaxf(m, sc);
        }
        #pragma unroll
        for (int off=1; off<16; off<<=1) m = fmaxf(m, __shfl_xor_sync(0xffffffffu, m, off));
        float sum = 0.f;
        #pragma unroll
        for (int c=0;c<4;c++){
            int j = jb*4 + c;
            float e = (j <= i) ? __expf(acc[r][c]-m) : 0.f;
            acc[r][c] = e; sum += e;
        }
        #pragma unroll
        for (int off=1; off<16; off<<=1) sum += __shfl_xor_sync(0xffffffffu, sum, off);
        float inv = 1.f/sum;
        #pragma unroll
        for (int c=0;c<4;c++) acc[r][c] *= inv;
    }
    __syncthreads();

    #pragma unroll
    for (int r=0;r<4;r++){
        float4 pv = make_float4(acc[r][0], acc[r][1], acc[r][2], acc[r][3]);
        *(float4*)&smA[(ib*4+r)*68 + jb*4] = pv;     // probs[i][j]
    }
    #pragma unroll
    for (int it = 0; it < 16; ++it){
        int idx = it*256 + t;
        int s = idx >> 6, d = idx & 63;
        smB[s*68 + d] = vb[s*256 + d];               // V[j][d]
    }
    __syncthreads();

    float o[4][4];
    #pragma unroll
    for (int r=0;r<4;r++)
        #pragma unroll
        for (int c=0;c<4;c++) o[r][c]=0.f;

    for (int j = 0; j < 64; ++j){
        float4 va = *(const float4*)&smB[j*68 + jb*4];
        float vv[4] = {va.x,va.y,va.z,va.w};
        float pa[4];
        #pragma unroll
        for (int r=0;r<4;r++) pa[r] = smA[(ib*4+r)*68 + j];
        #pragma unroll
        for (int r=0;r<4;r++)
            #pragma unroll
            for (int c=0;c<4;c++)
                o[r][c] += pa[r]*vv[c];
    }
    float* ob = g_q + (b*64)*256 + h*64;
    #pragma unroll
    for (int r=0;r<4;r++){
        float4 ov = make_float4(o[r][0],o[r][1],o[r][2],o[r][3]);
        *(float4*)&ob[(ib*4+r)*256 + jb*4] = ov;
    }
}

// ---------------------------------------------------------------------------
// scatter-max pooling: clustered[p,n,k,c] = max_s (1[hard==k] * x_attn)
// ---------------------------------------------------------------------------
__global__ void pool_kernel(){
    __shared__ int hs[64];
    int bx = blockIdx.x;
    int p = bx >> 6, n = bx & 63;
    int t = threadIdx.x;            // channel c
    if (t < 64) hs[t] = g_hard[(p*64+n)*64 + t];
    __syncthreads();
    int b = n*16 + p;
    float a0=-3.402823466e38f, a1=a0, a2=a0, a3=a0;
    for (int s = 0; s < 64; ++s){
        float v = g_x2[(b*64+s)*256 + t];
        int ks = hs[s];
        a0 = fmaxf(a0, ks==0 ? v : 0.f);
        a1 = fmaxf(a1, ks==1 ? v : 0.f);
        a2 = fmaxf(a2, ks==2 ? v : 0.f);
        a3 = fmaxf(a3, ks==3 ? v : 0.f);
    }
    int base = (p*64+n)*1024 + t;
    g_clus[base      ] = a0;
    g_clus[base + 256] = a1;
    g_clus[base + 512] = a2;
    g_clus[base + 768] = a3;
}

// ---------------------------------------------------------------------------
extern "C" void kernel_launch(void* const* d_in, const int* in_sizes, int n_in,
                              void* d_out, int out_size){
    const float* x   = (const float*)d_in[0];
    const float* pro = (const float*)d_in[1];
    const float* Wq  = (const float*)d_in[2];
    const float* bq  = (const float*)d_in[3];
    const float* Wk  = (const float*)d_in[4];
    const float* bk  = (const float*)d_in[5];
    const float* Wv  = (const float*)d_in[6];
    const float* bv  = (const float*)d_in[7];
    const float* Wo  = (const float*)d_in[8];
    const float* bo  = (const float*)d_in[9];
    const float* fcb = (const float*)d_in[10];
    float* out = (float*)d_out;

    (void)in_sizes; (void)n_in; (void)out_size;

    // x2 build + clustering (independent paths)
    transpose_kernel<<<dim3(8,8,64),256>>>(x);
    cluster_kernel<<<1024,256>>>(x, pro);
    mode_kernel<<<16,256>>>(out + Nn*Cc*Pp);   // cluster_indices tail as float

    // QKV projections: (65536 x 256) @ (256 x 256) + bias
    sgemm_kernel<<<dim3(512,4,1),256>>>(0, Wq, bq, 0, 1, nullptr, 1, MR, 256, 256, 0);
    sgemm_kernel<<<dim3(512,4,1),256>>>(0, Wk, bk, 0, 2, nullptr, 1, MR, 256, 256, 0);
    sgemm_kernel<<<dim3(512,4,1),256>>>(0, Wv, bv, 0, 3, nullptr, 1, MR, 256, 256, 0);

    // causal attention (writes into g_q)
    attn_kernel<<<dim3(Hh,Bb),256>>>();

    // out-proj + bias + residual, in place into g_x2
    sgemm_kernel<<<dim3(512,4,1),256>>>(1, Wo, bo, 1, 0, nullptr, 1, MR, 256, 256, 0);

    // scatter-max pooling, then per-part FC into d_out (stride 16 over p)
    pool_kernel<<<1024,256>>>();
    sgemm_kernel<<<dim3(1,4,16),256>>>(4, fcb, nullptr, 0, 5, out, 16, 64, 1024, 1024, 1);
}

// round 10
// speedup vs baseline: 1.1585x; 1.1585x over previous
#include <cuda_runtime.h>

// Problem constants
#define Nn 64
#define Cc 256
#define Ss 64
#define Pp 16
#define Kk 4
#define Hh 4
#define Dd 64
#define Bb (Nn*Pp)      // 1024
#define MR (Bb*Ss)      // 65536 rows for the big GEMMs

// Scratch (device-static; no allocations allowed)
__device__ float g_x2 [MR*Cc];   // x2, later x_attn (residual added in place)
__device__ float g_q  [MR*Cc];   // Q, later attention output (in place)
__device__ float g_k  [MR*Cc];
__device__ float g_v  [MR*Cc];
__device__ float g_clus[Pp*Nn*Kk*Cc];
__device__ int   g_hard[Pp*Nn*Ss];

// ---------------------------------------------------------------------------
// transpose: x (n,c,s,p) -> x2 (n*p, s, c)
// ---------------------------------------------------------------------------
__global__ void transpose_kernel(const float* __restrict__ x){
    __shared__ float tile[32][129];
    int n  = blockIdx.z;
    int c0 = blockIdx.x * 32;
    int sp0= blockIdx.y * 128;
    int t  = threadIdx.x;
    #pragma unroll
    for (int it = 0; it < 16; ++it){
        int idx = it*256 + t;
        int cl = idx >> 7, spl = idx & 127;
        tile[cl][spl] = x[(n*Cc + c0 + cl)*1024 + sp0 + spl];
    }
    __syncthreads();
    #pragma unroll
    for (int it = 0; it < 4; ++it){
        int spl = it*32 + (t >> 3);
        int cl  = (t & 7) * 4;
        int sp  = sp0 + spl;
        int s = sp >> 4, p = sp & 15;
        float4 v = make_float4(tile[cl][spl], tile[cl+1][spl],
                               tile[cl+2][spl], tile[cl+3][spl]);
        *(float4*)&g_x2[((n*Pp + p)*Ss + s)*Cc + c0 + cl] = v;
    }
}

// ---------------------------------------------------------------------------
// clustering
// ---------------------------------------------------------------------------
__global__ void cluster_kernel(const float* __restrict__ x,
                               const float* __restrict__ protos){
    __shared__ float mu[256], rs[256];
    __shared__ float pr[4][256];
    __shared__ float pn[4];
    int bx = blockIdx.x;
    int p = bx >> 6, n = bx & 63;
    int t = threadIdx.x;

    for (int i = t; i < 1024; i += 256) pr[i>>8][i&255] = protos[p*1024 + i];
    __syncthreads();
    if (t < 4){
        float s = 0.f;
        for (int c = 0; c < 256; ++c){ float v = pr[t][c]; s += v*v; }
        pn[t] = rsqrtf(s);
    }
    __syncthreads();
    for (int i = t; i < 1024; i += 256) pr[i>>8][i&255] *= pn[i>>8];

    {
        int c = t;
        const float* xp = x + (n*256 + c)*1024 + p;
        float s1 = 0.f, s2 = 0.f;
        for (int s = 0; s < 64; ++s){ float v = xp[s*16]; s1 += v; s2 += v*v; }
        float m = s1 * (1.f/64.f);
        float var = s2 * (1.f/64.f) - m*m;
        mu[c] = m; rs[c] = rsqrtf(var + 1e-5f);
    }
    __syncthreads();

    int s = t >> 2, q4 = t & 3;
    const float* xs = x + (n*256)*1024 + s*16 + p;
    float nr = 0.f, d0=0.f, d1=0.f, d2=0.f, d3=0.f;
    for (int cc = 0; cc < 64; ++cc){
        int c = cc*4 + q4;
        float v = (xs[c*1024] - mu[c]) * rs[c];
        nr += v*v;
        d0 += v*pr[0][c]; d1 += v*pr[1][c];
        d2 += v*pr[2][c]; d3 += v*pr[3][c];
    }
    #pragma unroll
    for (int off = 1; off < 4; off <<= 1){
        nr += __shfl_xor_sync(0xffffffffu, nr, off);
        d0 += __shfl_xor_sync(0xffffffffu, d0, off);
        d1 += __shfl_xor_sync(0xffffffffu, d1, off);
        d2 += __shfl_xor_sync(0xffffffffu, d2, off);
        d3 += __shfl_xor_sync(0xffffffffu, d3, off);
    }
    if (q4 == 0){
        float inv = rsqrtf(nr);
        float s0 = d0*inv, s1v = d1*inv, s2v = d2*inv, s3v = d3*inv;
        int best = 0; float bv = s0;
        if (s1v > bv){ bv = s1v; best = 1; }
        if (s2v > bv){ bv = s2v; best = 2; }
        if (s3v > bv){ bv = s3v; best = 3; }
        g_hard[(p*64 + n)*64 + s] = best;
    }
}

__global__ void mode_kernel(float* __restrict__ outTail){
    int t = blockIdx.x*256 + threadIdx.x;       // 4096 = n*s
    int n = t >> 6, s = t & 63;
    int cnt[4] = {0,0,0,0};
    #pragma unroll
    for (int p = 0; p < 16; ++p) cnt[g_hard[(p*64+n)*64 + s]]++;
    int best = 0, bv = cnt[0];
    if (cnt[1] > bv){ bv = cnt[1]; best = 1; }
    if (cnt[2] > bv){ bv = cnt[2]; best = 2; }
    if (cnt[3] > bv){ bv = cnt[3]; best = 3; }
    outTail[t] = (float)best;
}

// ---------------------------------------------------------------------------
__device__ __forceinline__ float* selbuf(int sel, float* ext){
    switch (sel){
        case 0: return g_x2;
        case 1: return g_q;
        case 2: return g_k;
        case 3: return g_v;
        case 4: return g_clus;
        default: return ext;
    }
}

// ---------------------------------------------------------------------------
// Big SGEMM: C(65536x256) = A(65536x256)*B(256x256) [+bias] [+res g_x2]
// BM=128, BN=128, BK=16, 256 threads, 8x8 per thread (split 4+4 frags),
// double-buffered smem, one sync per k-tile. All LDS.128 conflict-free.
// ---------------------------------------------------------------------------
__global__ void __launch_bounds__(256) sgemm128_kernel(
    int aSel, const float* __restrict__ Bm,
    const float* __restrict__ bias, int useRes, int cSel)
{
    __shared__ float As[2][16][132];
    __shared__ float Bs[2][16][128];
    const float* A = selbuf(aSel, nullptr);
    float* C = selbuf(cSel, nullptr);

    int mbase = blockIdx.x * 128;
    int nbase = blockIdx.y * 128;
    int t = threadIdx.x;
    int tx = t & 15, ty = t >> 4;

    int arow = t >> 1;
    int ak   = (t & 1) * 8;
    int brow = t >> 4;
    int bc4  = (t & 15) * 4;

    const float* aptr = A  + (mbase + arow)*256 + ak;
    const float* bptr = Bm + brow*256 + nbase + bc4;

    float acc[8][8];
    #pragma unroll
    for (int i=0;i<8;i++)
        #pragma unroll
        for (int j=0;j<8;j++) acc[i][j]=0.f;

    // prefetch tile 0
    float4 a0g = *(const float4*)aptr;
    float4 a1g = *(const float4*)(aptr + 4);
    float4 b0g = *(const float4*)bptr;
    float4 b1g = *(const float4*)(bptr + 64);

    As[0][ak+0][arow]=a0g.x; As[0][ak+1][arow]=a0g.y;
    As[0][ak+2][arow]=a0g.z; As[0][ak+3][arow]=a0g.w;
    As[0][ak+4][arow]=a1g.x; As[0][ak+5][arow]=a1g.y;
    As[0][ak+6][arow]=a1g.z; As[0][ak+7][arow]=a1g.w;
    *(float4*)&Bs[0][brow][bc4]      = b0g;
    *(float4*)&Bs[0][brow][64 + bc4] = b1g;
    __syncthreads();

    #pragma unroll 1
    for (int kt = 0; kt < 16; ++kt){
        int cur = kt & 1;
        if (kt < 15){
            aptr += 16;  bptr += 16*256;
            a0g = *(const float4*)aptr;
            a1g = *(const float4*)(aptr + 4);
            b0g = *(const float4*)bptr;
            b1g = *(const float4*)(bptr + 64);
        }
        #pragma unroll
        for (int k = 0; k < 16; ++k){
            float4 xa0 = *(const float4*)&As[cur][k][ty*4];
            float4 xa1 = *(const float4*)&As[cur][k][64 + ty*4];
            float4 xb0 = *(const float4*)&Bs[cur][k][tx*4];
            float4 xb1 = *(const float4*)&Bs[cur][k][64 + tx*4];
            float am[8] = {xa0.x,xa0.y,xa0.z,xa0.w, xa1.x,xa1.y,xa1.z,xa1.w};
            float bn[8] = {xb0.x,xb0.y,xb0.z,xb0.w, xb1.x,xb1.y,xb1.z,xb1.w};
            #pragma unroll
            for (int i=0;i<8;i++)
                #pragma unroll
                for (int j=0;j<8;j++)
                    acc[i][j] += am[i]*bn[j];
        }
        if (kt < 15){
            int nxt = cur ^ 1;
            As[nxt][ak+0][arow]=a0g.x; As[nxt][ak+1][arow]=a0g.y;
            As[nxt][ak+2][arow]=a0g.z; As[nxt][ak+3][arow]=a0g.w;
            As[nxt][ak+4][arow]=a1g.x; As[nxt][ak+5][arow]=a1g.y;
            As[nxt][ak+6][arow]=a1g.z; As[nxt][ak+7][arow]=a1g.w;
            *(float4*)&Bs[nxt][brow][bc4]      = b0g;
            *(float4*)&Bs[nxt][brow][64 + bc4] = b1g;
            __syncthreads();
        }
    }

    // epilogue
    float4 bias0 = make_float4(0.f,0.f,0.f,0.f), bias1 = bias0;
    if (bias){
        bias0 = *(const float4*)&bias[nbase + tx*4];
        bias1 = *(const float4*)&bias[nbase + 64 + tx*4];
    }
    float bb[8] = {bias0.x,bias0.y,bias0.z,bias0.w,
                   bias1.x,bias1.y,bias1.z,bias1.w};

    #pragma unroll
    for (int i=0;i<8;i++){
        int row = mbase + ((i < 4) ? (ty*4 + i) : (64 + ty*4 + i - 4));
        float* crow = C + row*256;
        const float* rrow = g_x2 + row*256;
        float4 v0 = make_float4(acc[i][0]+bb[0], acc[i][1]+bb[1],
                                acc[i][2]+bb[2], acc[i][3]+bb[3]);
        float4 v1 = make_float4(acc[i][4]+bb[4], acc[i][5]+bb[5],
                                acc[i][6]+bb[6], acc[i][7]+bb[7]);
        if (useRes){
            float4 r0 = *(const float4*)&rrow[nbase + tx*4];
            float4 r1 = *(const float4*)&rrow[nbase + 64 + tx*4];
            v0.x+=r0.x; v0.y+=r0.y; v0.z+=r0.z; v0.w+=r0.w;
            v1.x+=r1.x; v1.y+=r1.y; v1.z+=r1.z; v1.w+=r1.w;
        }
        *(float4*)&crow[nbase + tx*4]      = v0;
        *(float4*)&crow[nbase + 64 + tx*4] = v1;
    }
}

// ---------------------------------------------------------------------------
// small SGEMM (kept for the per-part FC: M=64 needs the guards)
// ---------------------------------------------------------------------------
__global__ void sgemm_kernel(int aSel, const float* __restrict__ Bm,
                             const float* __restrict__ bias, int useRes,
                             int cSel, float* extC, int cstride,
                             int M, int K, int lda, int perp)
{
    __shared__ float As[16][132];
    __shared__ float Bs[16][64];
    const float* A = selbuf(aSel, nullptr);
    float* C = selbuf(cSel, extC);
    const float* Bp = Bm;
    if (perp){
        int z = blockIdx.z;
        A  += z * 64 * 1024;
        Bp += z * 1024 * 256;
        C  += z;
    }
    int mbase = blockIdx.x * 128;
    int nbase = blockIdx.y * 64;
    int t = threadIdx.x;
    int tx = t & 15, ty = t >> 4;

    float acc[8][4];
    #pragma unroll
    for (int i=0;i<8;i++)
        #pragma unroll
        for (int j=0;j<4;j++) acc[i][j]=0.f;

    int arow = t >> 1;
    int ak   = (t & 1) * 8;
    int brow = t >> 4;
    int bc   = (t & 15) * 4;

    int ktiles = K >> 4;
    for (int kt = 0; kt < ktiles; ++kt){
        float4 a0, a1;
        if (mbase + arow < M){
            const float* ap = A + (mbase + arow)*lda + kt*16 + ak;
            a0 = *(const float4*)ap;
            a1 = *(const float4*)(ap + 4);
        } else {
            a0 = make_float4(0.f,0.f,0.f,0.f); a1 = a0;
        }
        As[ak+0][arow]=a0.x; As[ak+1][arow]=a0.y; As[ak+2][arow]=a0.z; As[ak+3][arow]=a0.w;
        As[ak+4][arow]=a1.x; As[ak+5][arow]=a1.y; As[ak+6][arow]=a1.z; As[ak+7][arow]=a1.w;
        *(float4*)&Bs[brow][bc] = *(const float4*)&Bp[(kt*16 + brow)*256 + nbase + bc];
        __syncthreads();
        #pragma unroll
        for (int k = 0; k < 16; ++k){
            float4 a0v = *(const float4*)&As[k][ty*8];
            float4 a1v = *(const float4*)&As[k][ty*8+4];
            float4 bv  = *(const float4*)&Bs[k][tx*4];
            float am[8] = {a0v.x,a0v.y,a0v.z,a0v.w,a1v.x,a1v.y,a1v.z,a1v.w};
            float bn[4] = {bv.x,bv.y,bv.z,bv.w};
            #pragma unroll
            for (int i=0;i<8;i++)
                #pragma unroll
                for (int j=0;j<4;j++)
                    acc[i][j] += am[i]*bn[j];
        }
        __syncthreads();
    }
    #pragma unroll
    for (int i=0;i<8;i++){
        int row = mbase + ty*8 + i;
        if (row >= M) continue;
        #pragma unroll
        for (int j=0;j<4;j++){
            int col = nbase + tx*4 + j;
            float v = acc[i][j];
            if (bias)   v += bias[col];
            if (useRes) v += g_x2[row*256 + col];
            C[(row*256 + col)*cstride] = v;
        }
    }
}

// ---------------------------------------------------------------------------
// causal attention per (b,h): S=64, D=64.
// ---------------------------------------------------------------------------
__global__ void attn_kernel(){
    __shared__ float smA[64*68];   // Q^T, then probs
    __shared__ float smB[64*68];   // K^T, then V
    int h = blockIdx.x, b = blockIdx.y;
    int t = threadIdx.x;
    const float* qb = g_q + (b*64)*256 + h*64;
    const float* kb = g_k + (b*64)*256 + h*64;
    const float* vb = g_v + (b*64)*256 + h*64;

    #pragma unroll
    for (int it = 0; it < 16; ++it){
        int idx = it*256 + t;
        int s = idx >> 6, d = idx & 63;
        smA[d*68 + s] = qb[s*256 + d];
        smB[d*68 + s] = kb[s*256 + d];
    }
    __syncthreads();

    int ib = t >> 4, jb = t & 15;
    float acc[4][4];
    #pragma unroll
    for (int r=0;r<4;r++)
        #pragma unroll
        for (int c=0;c<4;c++) acc[r][c]=0.f;

    for (int d = 0; d < 64; ++d){
        float4 qa = *(const float4*)&smA[d*68 + ib*4];
        float4 ka = *(const float4*)&smB[d*68 + jb*4];
        float qv[4] = {qa.x,qa.y,qa.z,qa.w};
        float kv[4] = {ka.x,ka.y,ka.z,ka.w};
        #pragma unroll
        for (int r=0;r<4;r++)
            #pragma unroll
            for (int c=0;c<4;c++)
                acc[r][c] += qv[r]*kv[c];
    }

    #pragma unroll
    for (int r=0;r<4;r++){
        int i = ib*4 + r;
        float m = -1e30f;
        #pragma unroll
        for (int c=0;c<4;c++){
            int j = jb*4 + c;
            float sc = (j <= i) ? acc[r][c]*0.125f : -1e30f;
            acc[r][c] = sc;
            m = fmaxf(m, sc);
        }
        #pragma unroll
        for (int off=1; off<16; off<<=1) m = fmaxf(m, __shfl_xor_sync(0xffffffffu, m, off));
        float sum = 0.f;
        #pragma unroll
        for (int c=0;c<4;c++){
            int j = jb*4 + c;
            float e = (j <= i) ? __expf(acc[r][c]-m) : 0.f;
            acc[r][c] = e; sum += e;
        }
        #pragma unroll
        for (int off=1; off<16; off<<=1) sum += __shfl_xor_sync(0xffffffffu, sum, off);
        float inv = 1.f/sum;
        #pragma unroll
        for (int c=0;c<4;c++) acc[r][c] *= inv;
    }
    __syncthreads();

    #pragma unroll
    for (int r=0;r<4;r++){
        float4 pv = make_float4(acc[r][0], acc[r][1], acc[r][2], acc[r][3]);
        *(float4*)&smA[(ib*4+r)*68 + jb*4] = pv;
    }
    #pragma unroll
    for (int it = 0; it < 16; ++it){
        int idx = it*256 + t;
        int s = idx >> 6, d = idx & 63;
        smB[s*68 + d] = vb[s*256 + d];
    }
    __syncthreads();

    float o[4][4];
    #pragma unroll
    for (int r=0;r<4;r++)
        #pragma unroll
        for (int c=0;c<4;c++) o[r][c]=0.f;

    for (int j = 0; j < 64; ++j){
        float4 va = *(const float4*)&smB[j*68 + jb*4];
        float vv[4] = {va.x,va.y,va.z,va.w};
        float pa[4];
        #pragma unroll
        for (int r=0;r<4;r++) pa[r] = smA[(ib*4+r)*68 + j];
        #pragma unroll
        for (int r=0;r<4;r++)
            #pragma unroll
            for (int c=0;c<4;c++)
                o[r][c] += pa[r]*vv[c];
    }
    float* ob = g_q + (b*64)*256 + h*64;
    #pragma unroll
    for (int r=0;r<4;r++){
        float4 ov = make_float4(o[r][0],o[r][1],o[r][2],o[r][3]);
        *(float4*)&ob[(ib*4+r)*256 + jb*4] = ov;
    }
}

// ---------------------------------------------------------------------------
// scatter-max pooling
// ---------------------------------------------------------------------------
__global__ void pool_kernel(){
    __shared__ int hs[64];
    int bx = blockIdx.x;
    int p = bx >> 6, n = bx & 63;
    int t = threadIdx.x;
    if (t < 64) hs[t] = g_hard[(p*64+n)*64 + t];
    __syncthreads();
    int b = n*16 + p;
    float a0=-3.402823466e38f, a1=a0, a2=a0, a3=a0;
    for (int s = 0; s < 64; ++s){
        float v = g_x2[(b*64+s)*256 + t];
        int ks = hs[s];
        a0 = fmaxf(a0, ks==0 ? v : 0.f);
        a1 = fmaxf(a1, ks==1 ? v : 0.f);
        a2 = fmaxf(a2, ks==2 ? v : 0.f);
        a3 = fmaxf(a3, ks==3 ? v : 0.f);
    }
    int base = (p*64+n)*1024 + t;
    g_clus[base      ] = a0;
    g_clus[base + 256] = a1;
    g_clus[base + 512] = a2;
    g_clus[base + 768] = a3;
}

// ---------------------------------------------------------------------------
extern "C" void kernel_launch(void* const* d_in, const int* in_sizes, int n_in,
                              void* d_out, int out_size){
    const float* x   = (const float*)d_in[0];
    const float* pro = (const float*)d_in[1];
    const float* Wq  = (const float*)d_in[2];
    const float* bq  = (const float*)d_in[3];
    const float* Wk  = (const float*)d_in[4];
    const float* bk  = (const float*)d_in[5];
    const float* Wv  = (const float*)d_in[6];
    const float* bv  = (const float*)d_in[7];
    const float* Wo  = (const float*)d_in[8];
    const float* bo  = (const float*)d_in[9];
    const float* fcb = (const float*)d_in[10];
    float* out = (float*)d_out;

    (void)in_sizes; (void)n_in; (void)out_size;

    transpose_kernel<<<dim3(8,8,64),256>>>(x);
    cluster_kernel<<<1024,256>>>(x, pro);
    mode_kernel<<<16,256>>>(out + Nn*Cc*Pp);

    // QKV projections: (65536 x 256) @ (256 x 256) + bias
    sgemm128_kernel<<<dim3(512,2),256>>>(0, Wq, bq, 0, 1);
    sgemm128_kernel<<<dim3(512,2),256>>>(0, Wk, bk, 0, 2);
    sgemm128_kernel<<<dim3(512,2),256>>>(0, Wv, bv, 0, 3);

    attn_kernel<<<dim3(Hh,Bb),256>>>();

    // out-proj + bias + residual, in place into g_x2
    sgemm128_kernel<<<dim3(512,2),256>>>(1, Wo, bo, 1, 0);

    pool_kernel<<<1024,256>>>();
    sgemm_kernel<<<dim3(1,4,16),256>>>(4, fcb, nullptr, 0, 5, out, 16, 64, 1024, 1024, 1);
}

// round 15
// speedup vs baseline: 1.2717x; 1.0977x over previous
#include <cuda_runtime.h>
#include <cuda_bf16.h>

// Problem constants
#define Nn 64
#define Cc 256
#define Ss 64
#define Pp 16
#define Kk 4
#define Hh 4
#define Dd 64
#define Bb (Nn*Pp)      // 1024
#define MR (Bb*Ss)      // 65536 rows for the big GEMMs

// Scratch (device-static; no allocations allowed)
__device__ float g_x2 [MR*Cc];   // x2, later x_attn (residual added in place)
__device__ float g_q  [MR*Cc];   // Q, later attention output (in place)
__device__ float g_k  [MR*Cc];
__device__ float g_v  [MR*Cc];
__device__ float g_clus[Pp*Nn*Kk*Cc];
__device__ int   g_hard[Pp*Nn*Ss];

// ---------------------------------------------------------------------------
// transpose: x (n,c,s,p) -> x2 (n*p, s, c)
// ---------------------------------------------------------------------------
__global__ void transpose_kernel(const float* __restrict__ x){
    __shared__ float tile[32][129];
    int n  = blockIdx.z;
    int c0 = blockIdx.x * 32;
    int sp0= blockIdx.y * 128;
    int t  = threadIdx.x;
    #pragma unroll
    for (int it = 0; it < 16; ++it){
        int idx = it*256 + t;
        int cl = idx >> 7, spl = idx & 127;
        tile[cl][spl] = x[(n*Cc + c0 + cl)*1024 + sp0 + spl];
    }
    __syncthreads();
    #pragma unroll
    for (int it = 0; it < 4; ++it){
        int spl = it*32 + (t >> 3);
        int cl  = (t & 7) * 4;
        int sp  = sp0 + spl;
        int s = sp >> 4, p = sp & 15;
        float4 v = make_float4(tile[cl][spl], tile[cl+1][spl],
                               tile[cl+2][spl], tile[cl+3][spl]);
        *(float4*)&g_x2[((n*Pp + p)*Ss + s)*Cc + c0 + cl] = v;
    }
}

// ---------------------------------------------------------------------------
// clustering
// ---------------------------------------------------------------------------
__global__ void cluster_kernel(const float* __restrict__ x,
                               const float* __restrict__ protos){
    __shared__ float mu[256], rs[256];
    __shared__ float pr[4][256];
    __shared__ float pn[4];
    int bx = blockIdx.x;
    int p = bx >> 6, n = bx & 63;
    int t = threadIdx.x;

    for (int i = t; i < 1024; i += 256) pr[i>>8][i&255] = protos[p*1024 + i];
    __syncthreads();
    if (t < 4){
        float s = 0.f;
        for (int c = 0; c < 256; ++c){ float v = pr[t][c]; s += v*v; }
        pn[t] = rsqrtf(s);
    }
    __syncthreads();
    for (int i = t; i < 1024; i += 256) pr[i>>8][i&255] *= pn[i>>8];

    {
        int c = t;
        const float* xp = x + (n*256 + c)*1024 + p;
        float s1 = 0.f, s2 = 0.f;
        for (int s = 0; s < 64; ++s){ float v = xp[s*16]; s1 += v; s2 += v*v; }
        float m = s1 * (1.f/64.f);
        float var = s2 * (1.f/64.f) - m*m;
        mu[c] = m; rs[c] = rsqrtf(var + 1e-5f);
    }
    __syncthreads();

    int s = t >> 2, q4 = t & 3;
    const float* xs = x + (n*256)*1024 + s*16 + p;
    float nr = 0.f, d0=0.f, d1=0.f, d2=0.f, d3=0.f;
    for (int cc = 0; cc < 64; ++cc){
        int c = cc*4 + q4;
        float v = (xs[c*1024] - mu[c]) * rs[c];
        nr += v*v;
        d0 += v*pr[0][c]; d1 += v*pr[1][c];
        d2 += v*pr[2][c]; d3 += v*pr[3][c];
    }
    #pragma unroll
    for (int off = 1; off < 4; off <<= 1){
        nr += __shfl_xor_sync(0xffffffffu, nr, off);
        d0 += __shfl_xor_sync(0xffffffffu, d0, off);
        d1 += __shfl_xor_sync(0xffffffffu, d1, off);
        d2 += __shfl_xor_sync(0xffffffffu, d2, off);
        d3 += __shfl_xor_sync(0xffffffffu, d3, off);
    }
    if (q4 == 0){
        float inv = rsqrtf(nr);
        float s0 = d0*inv, s1v = d1*inv, s2v = d2*inv, s3v = d3*inv;
        int best = 0; float bv = s0;
        if (s1v > bv){ bv = s1v; best = 1; }
        if (s2v > bv){ bv = s2v; best = 2; }
        if (s3v > bv){ bv = s3v; best = 3; }
        g_hard[(p*64 + n)*64 + s] = best;
    }
}

__global__ void mode_kernel(float* __restrict__ outTail){
    int t = blockIdx.x*256 + threadIdx.x;       // 4096 = n*s
    int n = t >> 6, s = t & 63;
    int cnt[4] = {0,0,0,0};
    #pragma unroll
    for (int p = 0; p < 16; ++p) cnt[g_hard[(p*64+n)*64 + s]]++;
    int best = 0, bv = cnt[0];
    if (cnt[1] > bv){ bv = cnt[1]; best = 1; }
    if (cnt[2] > bv){ bv = cnt[2]; best = 2; }
    if (cnt[3] > bv){ bv = cnt[3]; best = 3; }
    outTail[t] = (float)best;
}

// ---------------------------------------------------------------------------
__device__ __forceinline__ float* selbuf(int sel, float* ext){
    switch (sel){
        case 0: return g_x2;
        case 1: return g_q;
        case 2: return g_k;
        case 3: return g_v;
        case 4: return g_clus;
        default: return ext;
    }
}

// ===========================================================================
// mma.sync bf16 split GEMM: C(65536x256) = A(65536x256)*W(256x256) [+bias][+res]
// CTA tile 128x128, 8 warps (2M x 4N), warp tile 64x32, K chunks of 32.
// fp32 -> bf16 hi/lo split; D += Ah*Bh + Ah*Bl + Al*Bh (fp32 accumulate).
// Smem row stride 40 bf16 (80B = 20 banks) -> conflict-free frag loads.
// ===========================================================================
#define AST 40

__device__ __forceinline__ void mma16816(float* c, const unsigned* a, const unsigned* b){
    asm volatile(
        "mma.sync.aligned.m16n8k16.row.col.f32.bf16.bf16.f32 "
        "{%0,%1,%2,%3}, {%4,%5,%6,%7}, {%8,%9}, {%0,%1,%2,%3};"
        : "+f"(c[0]), "+f"(c[1]), "+f"(c[2]), "+f"(c[3])
        : "r"(a[0]), "r"(a[1]), "r"(a[2]), "r"(a[3]),
          "r"(b[0]), "r"(b[1]));
}
__device__ __forceinline__ void split2(float x, unsigned short& h, unsigned short& l){
    __nv_bfloat16 hb = __float2bfloat16(x);
    __nv_bfloat16 lb = __float2bfloat16(x - __bfloat162float(hb));
    h = __bfloat16_as_ushort(hb);
    l = __bfloat16_as_ushort(lb);
}

__global__ void __launch_bounds__(256) mgemm_kernel(
    int aSel, const float* __restrict__ W,
    const float* __restrict__ bias, int useRes, int cSel)
{
    __shared__ unsigned short Ah[128][AST], Al[128][AST];
    __shared__ unsigned short Bh[128][AST], Bl[128][AST];
    const float* A = selbuf(aSel, nullptr);
    float* C = selbuf(cSel, nullptr);

    int t = threadIdx.x, w = t >> 5, lane = t & 31;
    int g = lane >> 2, q = lane & 3;
    int mb = blockIdx.x * 128, nb = blockIdx.y * 128;
    int Mw = (w & 1) * 64, Nw = (w >> 1) * 32;

    float acc[4][4][4];
    #pragma unroll
    for (int mf = 0; mf < 4; ++mf)
        #pragma unroll
        for (int nf = 0; nf < 4; ++nf)
            #pragma unroll
            for (int r = 0; r < 4; ++r) acc[mf][nf][r] = 0.f;

    #pragma unroll 1
    for (int kc = 0; kc < 8; ++kc){
        // ---- A: 128 rows x 32 k fp32 -> hi/lo bf16 ----
        #pragma unroll
        for (int it = 0; it < 4; ++it){
            int idx = it*256 + t;           // 1024 float4
            int row = idx >> 3;
            int j4  = (idx & 7) * 4;
            float4 v = *(const float4*)&A[(mb + row)*256 + kc*32 + j4];
            unsigned short h0,h1,h2,h3,l0,l1,l2,l3;
            split2(v.x,h0,l0); split2(v.y,h1,l1);
            split2(v.z,h2,l2); split2(v.w,h3,l3);
            unsigned long long ph = (unsigned long long)h0 | ((unsigned long long)h1<<16)
                                  | ((unsigned long long)h2<<32) | ((unsigned long long)h3<<48);
            unsigned long long pl = (unsigned long long)l0 | ((unsigned long long)l1<<16)
                                  | ((unsigned long long)l2<<32) | ((unsigned long long)l3<<48);
            *(unsigned long long*)&Ah[row][j4] = ph;
            *(unsigned long long*)&Al[row][j4] = pl;
        }
        // ---- B: W[kc*32+kk][nb+n] -> Bsm[n][kk] (transpose) ----
        #pragma unroll
        for (int it = 0; it < 4; ++it){
            int idx = it*256 + t;           // 1024 (n, kk4) pairs
            int n   = idx & 127;
            int kk4 = (idx >> 7) * 4;
            float v0 = W[(kc*32 + kk4 + 0)*256 + nb + n];
            float v1 = W[(kc*32 + kk4 + 1)*256 + nb + n];
            float v2 = W[(kc*32 + kk4 + 2)*256 + nb + n];
            float v3 = W[(kc*32 + kk4 + 3)*256 + nb + n];
            unsigned short h0,h1,h2,h3,l0,l1,l2,l3;
            split2(v0,h0,l0); split2(v1,h1,l1);
            split2(v2,h2,l2); split2(v3,h3,l3);
            unsigned long long ph = (unsigned long long)h0 | ((unsigned long long)h1<<16)
                                  | ((unsigned long long)h2<<32) | ((unsigned long long)h3<<48);
            unsigned long long pl = (unsigned long long)l0 | ((unsigned long long)l1<<16)
                                  | ((unsigned long long)l2<<32) | ((unsigned long long)l3<<48);
            *(unsigned long long*)&Bh[n][kk4] = ph;
            *(unsigned long long*)&Bl[n][kk4] = pl;
        }
        __syncthreads();

        #pragma unroll
        for (int ks = 0; ks < 2; ++ks){
            int k0 = ks*16 + q*2;
            // B fragments for the 4 n-frags
            unsigned bh[4][2], bl[4][2];
            #pragma unroll
            for (int nf = 0; nf < 4; ++nf){
                int n = Nw + nf*8 + g;
                bh[nf][0] = *(const unsigned*)&Bh[n][k0];
                bh[nf][1] = *(const unsigned*)&Bh[n][k0+8];
                bl[nf][0] = *(const unsigned*)&Bl[n][k0];
                bl[nf][1] = *(const unsigned*)&Bl[n][k0+8];
            }
            #pragma unroll
            for (int mf = 0; mf < 4; ++mf){
                int r0 = Mw + mf*16 + g;
                unsigned ah[4], al[4];
                ah[0] = *(const unsigned*)&Ah[r0  ][k0];
                ah[1] = *(const unsigned*)&Ah[r0+8][k0];
                ah[2] = *(const unsigned*)&Ah[r0  ][k0+8];
                ah[3] = *(const unsigned*)&Ah[r0+8][k0+8];
                al[0] = *(const unsigned*)&Al[r0  ][k0];
                al[1] = *(const unsigned*)&Al[r0+8][k0];
                al[2] = *(const unsigned*)&Al[r0  ][k0+8];
                al[3] = *(const unsigned*)&Al[r0+8][k0+8];
                #pragma unroll
                for (int nf = 0; nf < 4; ++nf){
                    mma16816(acc[mf][nf], ah, bh[nf]);
                    mma16816(acc[mf][nf], ah, bl[nf]);
                    mma16816(acc[mf][nf], al, bh[nf]);
                }
            }
        }
        __syncthreads();
    }

    // ---- epilogue ----
    #pragma unroll
    for (int mf = 0; mf < 4; ++mf){
        int r0 = mb + Mw + mf*16 + g;
        #pragma unroll
        for (int nf = 0; nf < 4; ++nf){
            int c0i = nb + Nw + nf*8 + q*2;
            float b0 = 0.f, b1 = 0.f;
            if (bias){ b0 = bias[c0i]; b1 = bias[c0i+1]; }
            float v00 = acc[mf][nf][0] + b0, v01 = acc[mf][nf][1] + b1;
            float v10 = acc[mf][nf][2] + b0, v11 = acc[mf][nf][3] + b1;
            if (useRes){
                v00 += g_x2[r0*256 + c0i];     v01 += g_x2[r0*256 + c0i + 1];
                v10 += g_x2[(r0+8)*256 + c0i]; v11 += g_x2[(r0+8)*256 + c0i + 1];
            }
            *(float2*)&C[r0*256 + c0i]     = make_float2(v00, v01);
            *(float2*)&C[(r0+8)*256 + c0i] = make_float2(v10, v11);
        }
    }
}

// ---------------------------------------------------------------------------
// small SGEMM (kept for the per-part FC: M=64 needs the guards)
// ---------------------------------------------------------------------------
__global__ void sgemm_kernel(int aSel, const float* __restrict__ Bm,
                             const float* __restrict__ bias, int useRes,
                             int cSel, float* extC, int cstride,
                             int M, int K, int lda, int perp)
{
    __shared__ float As[16][132];
    __shared__ float Bs[16][64];
    const float* A = selbuf(aSel, nullptr);
    float* C = selbuf(cSel, extC);
    const float* Bp = Bm;
    if (perp){
        int z = blockIdx.z;
        A  += z * 64 * 1024;
        Bp += z * 1024 * 256;
        C  += z;
    }
    int mbase = blockIdx.x * 128;
    int nbase = blockIdx.y * 64;
    int t = threadIdx.x;
    int tx = t & 15, ty = t >> 4;

    float acc[8][4];
    #pragma unroll
    for (int i=0;i<8;i++)
        #pragma unroll
        for (int j=0;j<4;j++) acc[i][j]=0.f;

    int arow = t >> 1;
    int ak   = (t & 1) * 8;
    int brow = t >> 4;
    int bc   = (t & 15) * 4;

    int ktiles = K >> 4;
    for (int kt = 0; kt < ktiles; ++kt){
        float4 a0, a1;
        if (mbase + arow < M){
            const float* ap = A + (mbase + arow)*lda + kt*16 + ak;
            a0 = *(const float4*)ap;
            a1 = *(const float4*)(ap + 4);
        } else {
            a0 = make_float4(0.f,0.f,0.f,0.f); a1 = a0;
        }
        As[ak+0][arow]=a0.x; As[ak+1][arow]=a0.y; As[ak+2][arow]=a0.z; As[ak+3][arow]=a0.w;
        As[ak+4][arow]=a1.x; As[ak+5][arow]=a1.y; As[ak+6][arow]=a1.z; As[ak+7][arow]=a1.w;
        *(float4*)&Bs[brow][bc] = *(const float4*)&Bp[(kt*16 + brow)*256 + nbase + bc];
        __syncthreads();
        #pragma unroll
        for (int k = 0; k < 16; ++k){
            float4 a0v = *(const float4*)&As[k][ty*8];
            float4 a1v = *(const float4*)&As[k][ty*8+4];
            float4 bv  = *(const float4*)&Bs[k][tx*4];
            float am[8] = {a0v.x,a0v.y,a0v.z,a0v.w,a1v.x,a1v.y,a1v.z,a1v.w};
            float bn[4] = {bv.x,bv.y,bv.z,bv.w};
            #pragma unroll
            for (int i=0;i<8;i++)
                #pragma unroll
                for (int j=0;j<4;j++)
                    acc[i][j] += am[i]*bn[j];
        }
        __syncthreads();
    }
    #pragma unroll
    for (int i=0;i<8;i++){
        int row = mbase + ty*8 + i;
        if (row >= M) continue;
        #pragma unroll
        for (int j=0;j<4;j++){
            int col = nbase + tx*4 + j;
            float v = acc[i][j];
            if (bias)   v += bias[col];
            if (useRes) v += g_x2[row*256 + col];
            C[(row*256 + col)*cstride] = v;
        }
    }
}

// ---------------------------------------------------------------------------
// causal attention per (b,h): S=64, D=64.
// ---------------------------------------------------------------------------
__global__ void attn_kernel(){
    __shared__ float smA[64*68];   // Q^T, then probs
    __shared__ float smB[64*68];   // K^T, then V
    int h = blockIdx.x, b = blockIdx.y;
    int t = threadIdx.x;
    const float* qb = g_q + (b*64)*256 + h*64;
    const float* kb = g_k + (b*64)*256 + h*64;
    const float* vb = g_v + (b*64)*256 + h*64;

    #pragma unroll
    for (int it = 0; it < 16; ++it){
        int idx = it*256 + t;
        int s = idx >> 6, d = idx & 63;
        smA[d*68 + s] = qb[s*256 + d];
        smB[d*68 + s] = kb[s*256 + d];
    }
    __syncthreads();

    int ib = t >> 4, jb = t & 15;
    float acc[4][4];
    #pragma unroll
    for (int r=0;r<4;r++)
        #pragma unroll
        for (int c=0;c<4;c++) acc[r][c]=0.f;

    for (int d = 0; d < 64; ++d){
        float4 qa = *(const float4*)&smA[d*68 + ib*4];
        float4 ka = *(const float4*)&smB[d*68 + jb*4];
        float qv[4] = {qa.x,qa.y,qa.z,qa.w};
        float kv[4] = {ka.x,ka.y,ka.z,ka.w};
        #pragma unroll
        for (int r=0;r<4;r++)
            #pragma unroll
            for (int c=0;c<4;c++)
                acc[r][c] += qv[r]*kv[c];
    }

    #pragma unroll
    for (int r=0;r<4;r++){
        int i = ib*4 + r;
        float m = -1e30f;
        #pragma unroll
        for (int c=0;c<4;c++){
            int j = jb*4 + c;
            float sc = (j <= i) ? acc[r][c]*0.125f : -1e30f;
            acc[r][c] = sc;
            m = fmaxf(m, sc);
        }
        #pragma unroll
        for (int off=1; off<16; off<<=1) m = fmaxf(m, __shfl_xor_sync(0xffffffffu, m, off));
        float sum = 0.f;
        #pragma unroll
        for (int c=0;c<4;c++){
            int j = jb*4 + c;
            float e = (j <= i) ? __expf(acc[r][c]-m) : 0.f;
            acc[r][c] = e; sum += e;
        }
        #pragma unroll
        for (int off=1; off<16; off<<=1) sum += __shfl_xor_sync(0xffffffffu, sum, off);
        float inv = 1.f/sum;
        #pragma unroll
        for (int c=0;c<4;c++) acc[r][c] *= inv;
    }
    __syncthreads();

    #pragma unroll
    for (int r=0;r<4;r++){
        float4 pv = make_float4(acc[r][0], acc[r][1], acc[r][2], acc[r][3]);
        *(float4*)&smA[(ib*4+r)*68 + jb*4] = pv;
    }
    #pragma unroll
    for (int it = 0; it < 16; ++it){
        int idx = it*256 + t;
        int s = idx >> 6, d = idx & 63;
        smB[s*68 + d] = vb[s*256 + d];
    }
    __syncthreads();

    float o[4][4];
    #pragma unroll
    for (int r=0;r<4;r++)
        #pragma unroll
        for (int c=0;c<4;c++) o[r][c]=0.f;

    for (int j = 0; j < 64; ++j){
        float4 va = *(const float4*)&smB[j*68 + jb*4];
        float vv[4] = {va.x,va.y,va.z,va.w};
        float pa[4];
        #pragma unroll
        for (int r=0;r<4;r++) pa[r] = smA[(ib*4+r)*68 + j];
        #pragma unroll
        for (int r=0;r<4;r++)
            #pragma unroll
            for (int c=0;c<4;c++)
                o[r][c] += pa[r]*vv[c];
    }
    float* ob = g_q + (b*64)*256 + h*64;
    #pragma unroll
    for (int r=0;r<4;r++){
        float4 ov = make_float4(o[r][0],o[r][1],o[r][2],o[r][3]);
        *(float4*)&ob[(ib*4+r)*256 + jb*4] = ov;
    }
}

// ---------------------------------------------------------------------------
// scatter-max pooling
// ---------------------------------------------------------------------------
__global__ void pool_kernel(){
    __shared__ int hs[64];
    int bx = blockIdx.x;
    int p = bx >> 6, n = bx & 63;
    int t = threadIdx.x;
    if (t < 64) hs[t] = g_hard[(p*64+n)*64 + t];
    __syncthreads();
    int b = n*16 + p;
    float a0=-3.402823466e38f, a1=a0, a2=a0, a3=a0;
    for (int s = 0; s < 64; ++s){
        float v = g_x2[(b*64+s)*256 + t];
        int ks = hs[s];
        a0 = fmaxf(a0, ks==0 ? v : 0.f);
        a1 = fmaxf(a1, ks==1 ? v : 0.f);
        a2 = fmaxf(a2, ks==2 ? v : 0.f);
        a3 = fmaxf(a3, ks==3 ? v : 0.f);
    }
    int base = (p*64+n)*1024 + t;
    g_clus[base      ] = a0;
    g_clus[base + 256] = a1;
    g_clus[base + 512] = a2;
    g_clus[base + 768] = a3;
}

// ---------------------------------------------------------------------------
extern "C" void kernel_launch(void* const* d_in, const int* in_sizes, int n_in,
                              void* d_out, int out_size){
    const float* x   = (const float*)d_in[0];
    const float* pro = (const float*)d_in[1];
    const float* Wq  = (const float*)d_in[2];
    const float* bq  = (const float*)d_in[3];
    const float* Wk  = (const float*)d_in[4];
    const float* bk  = (const float*)d_in[5];
    const float* Wv  = (const float*)d_in[6];
    const float* bv  = (const float*)d_in[7];
    const float* Wo  = (const float*)d_in[8];
    const float* bo  = (const float*)d_in[9];
    const float* fcb = (const float*)d_in[10];
    float* out = (float*)d_out;

    (void)in_sizes; (void)n_in; (void)out_size;

    transpose_kernel<<<dim3(8,8,64),256>>>(x);
    cluster_kernel<<<1024,256>>>(x, pro);
    mode_kernel<<<16,256>>>(out + Nn*Cc*Pp);

    // QKV projections on HMMA (split-bf16): (65536 x 256) @ (256 x 256) + bias
    mgemm_kernel<<<dim3(512,2),256>>>(0, Wq, bq, 0, 1);
    mgemm_kernel<<<dim3(512,2),256>>>(0, Wk, bk, 0, 2);
    mgemm_kernel<<<dim3(512,2),256>>>(0, Wv, bv, 0, 3);

    attn_kernel<<<dim3(Hh,Bb),256>>>();

    // out-proj + bias + residual, in place into g_x2
    mgemm_kernel<<<dim3(512,2),256>>>(1, Wo, bo, 1, 0);

    pool_kernel<<<1024,256>>>();
    sgemm_kernel<<<dim3(1,4,16),256>>>(4, fcb, nullptr, 0, 5, out, 16, 64, 1024, 1024, 1);
}

// round 16
// speedup vs baseline: 1.4284x; 1.1232x over previous
#include <cuda_runtime.h>
#include <cuda_bf16.h>

// Problem constants
#define Nn 64
#define Cc 256
#define Ss 64
#define Pp 16
#define Kk 4
#define Hh 4
#define Dd 64
#define Bb (Nn*Pp)      // 1024
#define MR (Bb*Ss)      // 65536 rows for the big GEMMs

// Scratch (device-static; no allocations allowed)
__device__ float g_x2 [MR*Cc];
__device__ float g_q  [MR*Cc];
__device__ float g_k  [MR*Cc];
__device__ float g_v  [MR*Cc];
__device__ float g_clus[Pp*Nn*Kk*Cc];
__device__ int   g_hard[Pp*Nn*Ss];
// pre-converted transposed weights: [slot][n*256+k], bf16 hi/lo
__device__ unsigned short g_wth[4*65536];
__device__ unsigned short g_wtl[4*65536];

// ---------------------------------------------------------------------------
// transpose: x (n,c,s,p) -> x2 (n*p, s, c)
// ---------------------------------------------------------------------------
__global__ void transpose_kernel(const float* __restrict__ x){
    __shared__ float tile[32][129];
    int n  = blockIdx.z;
    int c0 = blockIdx.x * 32;
    int sp0= blockIdx.y * 128;
    int t  = threadIdx.x;
    #pragma unroll
    for (int it = 0; it < 16; ++it){
        int idx = it*256 + t;
        int cl = idx >> 7, spl = idx & 127;
        tile[cl][spl] = x[(n*Cc + c0 + cl)*1024 + sp0 + spl];
    }
    __syncthreads();
    #pragma unroll
    for (int it = 0; it < 4; ++it){
        int spl = it*32 + (t >> 3);
        int cl  = (t & 7) * 4;
        int sp  = sp0 + spl;
        int s = sp >> 4, p = sp & 15;
        float4 v = make_float4(tile[cl][spl], tile[cl+1][spl],
                               tile[cl+2][spl], tile[cl+3][spl]);
        *(float4*)&g_x2[((n*Pp + p)*Ss + s)*Cc + c0 + cl] = v;
    }
}

// ---------------------------------------------------------------------------
// clustering
// ---------------------------------------------------------------------------
__global__ void cluster_kernel(const float* __restrict__ x,
                               const float* __restrict__ protos){
    __shared__ float mu[256], rs[256];
    __shared__ float pr[4][256];
    __shared__ float pn[4];
    int bx = blockIdx.x;
    int p = bx >> 6, n = bx & 63;
    int t = threadIdx.x;

    for (int i = t; i < 1024; i += 256) pr[i>>8][i&255] = protos[p*1024 + i];
    __syncthreads();
    if (t < 4){
        float s = 0.f;
        for (int c = 0; c < 256; ++c){ float v = pr[t][c]; s += v*v; }
        pn[t] = rsqrtf(s);
    }
    __syncthreads();
    for (int i = t; i < 1024; i += 256) pr[i>>8][i&255] *= pn[i>>8];

    {
        int c = t;
        const float* xp = x + (n*256 + c)*1024 + p;
        float s1 = 0.f, s2 = 0.f;
        for (int s = 0; s < 64; ++s){ float v = xp[s*16]; s1 += v; s2 += v*v; }
        float m = s1 * (1.f/64.f);
        float var = s2 * (1.f/64.f) - m*m;
        mu[c] = m; rs[c] = rsqrtf(var + 1e-5f);
    }
    __syncthreads();

    int s = t >> 2, q4 = t & 3;
    const float* xs = x + (n*256)*1024 + s*16 + p;
    float nr = 0.f, d0=0.f, d1=0.f, d2=0.f, d3=0.f;
    for (int cc = 0; cc < 64; ++cc){
        int c = cc*4 + q4;
        float v = (xs[c*1024] - mu[c]) * rs[c];
        nr += v*v;
        d0 += v*pr[0][c]; d1 += v*pr[1][c];
        d2 += v*pr[2][c]; d3 += v*pr[3][c];
    }
    #pragma unroll
    for (int off = 1; off < 4; off <<= 1){
        nr += __shfl_xor_sync(0xffffffffu, nr, off);
        d0 += __shfl_xor_sync(0xffffffffu, d0, off);
        d1 += __shfl_xor_sync(0xffffffffu, d1, off);
        d2 += __shfl_xor_sync(0xffffffffu, d2, off);
        d3 += __shfl_xor_sync(0xffffffffu, d3, off);
    }
    if (q4 == 0){
        float inv = rsqrtf(nr);
        float s0 = d0*inv, s1v = d1*inv, s2v = d2*inv, s3v = d3*inv;
        int best = 0; float bv = s0;
        if (s1v > bv){ bv = s1v; best = 1; }
        if (s2v > bv){ bv = s2v; best = 2; }
        if (s3v > bv){ bv = s3v; best = 3; }
        g_hard[(p*64 + n)*64 + s] = best;
    }
}

__global__ void mode_kernel(float* __restrict__ outTail){
    int t = blockIdx.x*256 + threadIdx.x;       // 4096 = n*s
    int n = t >> 6, s = t & 63;
    int cnt[4] = {0,0,0,0};
    #pragma unroll
    for (int p = 0; p < 16; ++p) cnt[g_hard[(p*64+n)*64 + s]]++;
    int best = 0, bv = cnt[0];
    if (cnt[1] > bv){ bv = cnt[1]; best = 1; }
    if (cnt[2] > bv){ bv = cnt[2]; best = 2; }
    if (cnt[3] > bv){ bv = cnt[3]; best = 3; }
    outTail[t] = (float)best;
}

// ---------------------------------------------------------------------------
__device__ __forceinline__ float* selbuf(int sel, float* ext){
    switch (sel){
        case 0: return g_x2;
        case 1: return g_q;
        case 2: return g_k;
        case 3: return g_v;
        case 4: return g_clus;
        default: return ext;
    }
}

__device__ __forceinline__ unsigned smem_u32(const void* p){
    unsigned a;
    asm("{ .reg .u64 t; cvta.to.shared.u64 t, %1; cvt.u32.u64 %0, t; }"
        : "=r"(a) : "l"(p));
    return a;
}
__device__ __forceinline__ void split2(float x, unsigned short& h, unsigned short& l){
    __nv_bfloat16 hb = __float2bfloat16(x);
    __nv_bfloat16 lb = __float2bfloat16(x - __bfloat162float(hb));
    h = __bfloat16_as_ushort(hb);
    l = __bfloat16_as_ushort(lb);
}
__device__ __forceinline__ void mma16816(float* c, const unsigned* a, const unsigned* b){
    asm volatile(
        "mma.sync.aligned.m16n8k16.row.col.f32.bf16.bf16.f32 "
        "{%0,%1,%2,%3}, {%4,%5,%6,%7}, {%8,%9}, {%0,%1,%2,%3};"
        : "+f"(c[0]), "+f"(c[1]), "+f"(c[2]), "+f"(c[3])
        : "r"(a[0]), "r"(a[1]), "r"(a[2]), "r"(a[3]),
          "r"(b[0]), "r"(b[1]));
}

// ---------------------------------------------------------------------------
// wconv: W[k][n] fp32 -> g_wth/g_wtl[slot][n][k] bf16 hi/lo (transposed)
// grid 16 blocks (4 k-tiles x 4 n-tiles), 256 threads.
// ---------------------------------------------------------------------------
__global__ void wconv_kernel(const float* __restrict__ W, int slot){
    __shared__ unsigned short shh[64][65], shl[64][65];
    int k0 = (blockIdx.x & 3) * 64;
    int n0 = (blockIdx.x >> 2) * 64;
    int t = threadIdx.x;
    #pragma unroll
    for (int it = 0; it < 16; ++it){
        int idx = it*256 + t;
        int kk = idx >> 6, nn = idx & 63;
        float v = W[(k0 + kk)*256 + n0 + nn];
        unsigned short h, l; split2(v, h, l);
        shh[nn][kk] = h; shl[nn][kk] = l;
    }
    __syncthreads();
    #pragma unroll
    for (int it = 0; it < 2; ++it){
        int idx = it*256 + t;          // 512 = 64 rows x 8 segs
        int row = idx >> 3, seg = idx & 7;
        unsigned short th[8], tl[8];
        #pragma unroll
        for (int e = 0; e < 8; ++e){
            th[e] = shh[row][seg*8 + e];
            tl[e] = shl[row][seg*8 + e];
        }
        int o = slot*65536 + (n0 + row)*256 + k0 + seg*8;
        *(uint4*)&g_wth[o] = *(uint4*)th;
        *(uint4*)&g_wtl[o] = *(uint4*)tl;
    }
}

// ===========================================================================
// mgemm: C(65536x256) = A * W [+bias][+res] — HMMA split-bf16, pipelined.
// CTA 128x128, 8 warps (2M x 4N), K chunks of 32, double-buffered dynamic smem.
// B from pre-converted g_wth/g_wtl via cp.async; A fp32 LDG prefetch -> split.
// smem layout per buffer: Ah[128][40] Al Bh Bl (5120 shorts each, 40960 B/buf).
// ===========================================================================
#define AST 40
#define TILE_SH 5120
#define BUF_SH  20480
#define MG_SMEM (2*BUF_SH*2)   // bytes: 2 buffers * 20480 shorts * 2B = 81920

__global__ void __launch_bounds__(256) mgemm_kernel(
    int aSel, int wSlot, const float* __restrict__ bias, int useRes, int cSel)
{
    extern __shared__ unsigned short sm[];
    const float* A = selbuf(aSel, nullptr);
    float* C = selbuf(cSel, nullptr);
    const unsigned short* WH = g_wth + wSlot*65536;
    const unsigned short* WL = g_wtl + wSlot*65536;

    int t = threadIdx.x, w = t >> 5, lane = t & 31;
    int g = lane >> 2, q = lane & 3;
    int mb = blockIdx.x * 128, nb = blockIdx.y * 128;
    int Mw = (w & 1) * 64, Nw = (w >> 1) * 32;

    float acc[4][4][4];
    #pragma unroll
    for (int mf = 0; mf < 4; ++mf)
        #pragma unroll
        for (int nf = 0; nf < 4; ++nf)
            #pragma unroll
            for (int r = 0; r < 4; ++r) acc[mf][nf][r] = 0.f;

    // per-thread A mapping: 4 float4 loads (row, j4)
    int arow0 = t >> 1;                 // rows t>>1 + {0,128? no}
    (void)arow0;

    float4 apf[4];

    // ---- helpers inlined ----
    // issue cp.async for B chunk kc into buffer buf
    auto issueB = [&](int kc, int buf){
        unsigned short* Bh = sm + buf*BUF_SH + 2*TILE_SH;
        unsigned short* Bl = sm + buf*BUF_SH + 3*TILE_SH;
        #pragma unroll
        for (int it = 0; it < 2; ++it){
            int idx = it*256 + t;       // 512: n = idx>>2, seg = idx&3
            int n = idx >> 2, seg = idx & 3;
            unsigned dh = smem_u32(&Bh[n*AST + seg*8]);
            unsigned dl = smem_u32(&Bl[n*AST + seg*8]);
            const unsigned short* sh = &WH[(nb + n)*256 + kc*32 + seg*8];
            const unsigned short* sl = &WL[(nb + n)*256 + kc*32 + seg*8];
            asm volatile("cp.async.ca.shared.global [%0], [%1], 16;" :: "r"(dh), "l"(sh));
            asm volatile("cp.async.ca.shared.global [%0], [%1], 16;" :: "r"(dl), "l"(sl));
        }
        asm volatile("cp.async.commit_group;" ::: "memory");
    };
    auto loadA = [&](int kc){
        #pragma unroll
        for (int it = 0; it < 4; ++it){
            int idx = it*256 + t;
            int row = idx >> 3, j4 = (idx & 7) * 4;
            apf[it] = *(const float4*)&A[(mb + row)*256 + kc*32 + j4];
        }
    };
    auto storeA = [&](int buf){
        unsigned short* Ah = sm + buf*BUF_SH;
        unsigned short* Al = sm + buf*BUF_SH + TILE_SH;
        #pragma unroll
        for (int it = 0; it < 4; ++it){
            int idx = it*256 + t;
            int row = idx >> 3, j4 = (idx & 7) * 4;
            float vv[4] = {apf[it].x, apf[it].y, apf[it].z, apf[it].w};
            unsigned long long ph = 0ull, pl = 0ull;
            #pragma unroll
            for (int e = 0; e < 4; ++e){
                unsigned short h, l; split2(vv[e], h, l);
                ph |= (unsigned long long)h << (16*e);
                pl |= (unsigned long long)l << (16*e);
            }
            *(unsigned long long*)&Ah[row*AST + j4] = ph;
            *(unsigned long long*)&Al[row*AST + j4] = pl;
        }
    };

    // ---- prologue: fill buffer 0 with chunk 0 ----
    loadA(0);
    storeA(0);
    issueB(0, 0);
    asm volatile("cp.async.wait_group 0;" ::: "memory");
    __syncthreads();

    #pragma unroll 1
    for (int kc = 0; kc < 8; ++kc){
        int buf = kc & 1;
        if (kc < 7){
            issueB(kc + 1, buf ^ 1);
            loadA(kc + 1);
        }
        // ---- MMA phase on smem[buf] ----
        {
            const unsigned short* Ah = sm + buf*BUF_SH;
            const unsigned short* Al = Ah + TILE_SH;
            const unsigned short* Bh = Ah + 2*TILE_SH;
            const unsigned short* Bl = Ah + 3*TILE_SH;
            #pragma unroll
            for (int ks = 0; ks < 2; ++ks){
                int k0 = ks*16 + q*2;
                unsigned bh[4][2], bl[4][2];
                #pragma unroll
                for (int nf = 0; nf < 4; ++nf){
                    int n = Nw + nf*8 + g;
                    bh[nf][0] = *(const unsigned*)&Bh[n*AST + k0];
                    bh[nf][1] = *(const unsigned*)&Bh[n*AST + k0 + 8];
                    bl[nf][0] = *(const unsigned*)&Bl[n*AST + k0];
                    bl[nf][1] = *(const unsigned*)&Bl[n*AST + k0 + 8];
                }
                #pragma unroll
                for (int mf = 0; mf < 4; ++mf){
                    int r0 = Mw + mf*16 + g;
                    unsigned ah[4], al[4];
                    ah[0] = *(const unsigned*)&Ah[(r0    )*AST + k0];
                    ah[1] = *(const unsigned*)&Ah[(r0 + 8)*AST + k0];
                    ah[2] = *(const unsigned*)&Ah[(r0    )*AST + k0 + 8];
                    ah[3] = *(const unsigned*)&Ah[(r0 + 8)*AST + k0 + 8];
                    al[0] = *(const unsigned*)&Al[(r0    )*AST + k0];
                    al[1] = *(const unsigned*)&Al[(r0 + 8)*AST + k0];
                    al[2] = *(const unsigned*)&Al[(r0    )*AST + k0 + 8];
                    al[3] = *(const unsigned*)&Al[(r0 + 8)*AST + k0 + 8];
                    #pragma unroll
                    for (int nf = 0; nf < 4; ++nf){
                        mma16816(acc[mf][nf], ah, bh[nf]);
                        mma16816(acc[mf][nf], ah, bl[nf]);
                        mma16816(acc[mf][nf], al, bh[nf]);
                    }
                }
            }
        }
        if (kc < 7){
            asm volatile("cp.async.wait_group 0;" ::: "memory");
            storeA(buf ^ 1);
        }
        __syncthreads();
    }

    // ---- epilogue ----
    #pragma unroll
    for (int mf = 0; mf < 4; ++mf){
        int r0 = mb + Mw + mf*16 + g;
        #pragma unroll
        for (int nf = 0; nf < 4; ++nf){
            int c0i = nb + Nw + nf*8 + q*2;
            float b0 = 0.f, b1 = 0.f;
            if (bias){ b0 = bias[c0i]; b1 = bias[c0i+1]; }
            float v00 = acc[mf][nf][0] + b0, v01 = acc[mf][nf][1] + b1;
            float v10 = acc[mf][nf][2] + b0, v11 = acc[mf][nf][3] + b1;
            if (useRes){
                v00 += g_x2[r0*256 + c0i];     v01 += g_x2[r0*256 + c0i + 1];
                v10 += g_x2[(r0+8)*256 + c0i]; v11 += g_x2[(r0+8)*256 + c0i + 1];
            }
            *(float2*)&C[r0*256 + c0i]     = make_float2(v00, v01);
            *(float2*)&C[(r0+8)*256 + c0i] = make_float2(v10, v11);
        }
    }
}

// ---------------------------------------------------------------------------
// small SGEMM (kept for the per-part FC: M=64 needs the guards)
// ---------------------------------------------------------------------------
__global__ void sgemm_kernel(int aSel, const float* __restrict__ Bm,
                             const float* __restrict__ bias, int useRes,
                             int cSel, float* extC, int cstride,
                             int M, int K, int lda, int perp)
{
    __shared__ float As[16][132];
    __shared__ float Bs[16][64];
    const float* A = selbuf(aSel, nullptr);
    float* C = selbuf(cSel, extC);
    const float* Bp = Bm;
    if (perp){
        int z = blockIdx.z;
        A  += z * 64 * 1024;
        Bp += z * 1024 * 256;
        C  += z;
    }
    int mbase = blockIdx.x * 128;
    int nbase = blockIdx.y * 64;
    int t = threadIdx.x;
    int tx = t & 15, ty = t >> 4;

    float acc[8][4];
    #pragma unroll
    for (int i=0;i<8;i++)
        #pragma unroll
        for (int j=0;j<4;j++) acc[i][j]=0.f;

    int arow = t >> 1;
    int ak   = (t & 1) * 8;
    int brow = t >> 4;
    int bc   = (t & 15) * 4;

    int ktiles = K >> 4;
    for (int kt = 0; kt < ktiles; ++kt){
        float4 a0, a1;
        if (mbase + arow < M){
            const float* ap = A + (mbase + arow)*lda + kt*16 + ak;
            a0 = *(const float4*)ap;
            a1 = *(const float4*)(ap + 4);
        } else {
            a0 = make_float4(0.f,0.f,0.f,0.f); a1 = a0;
        }
        As[ak+0][arow]=a0.x; As[ak+1][arow]=a0.y; As[ak+2][arow]=a0.z; As[ak+3][arow]=a0.w;
        As[ak+4][arow]=a1.x; As[ak+5][arow]=a1.y; As[ak+6][arow]=a1.z; As[ak+7][arow]=a1.w;
        *(float4*)&Bs[brow][bc] = *(const float4*)&Bp[(kt*16 + brow)*256 + nbase + bc];
        __syncthreads();
        #pragma unroll
        for (int k = 0; k < 16; ++k){
            float4 a0v = *(const float4*)&As[k][ty*8];
            float4 a1v = *(const float4*)&As[k][ty*8+4];
            float4 bv  = *(const float4*)&Bs[k][tx*4];
            float am[8] = {a0v.x,a0v.y,a0v.z,a0v.w,a1v.x,a1v.y,a1v.z,a1v.w};
            float bn[4] = {bv.x,bv.y,bv.z,bv.w};
            #pragma unroll
            for (int i=0;i<8;i++)
                #pragma unroll
                for (int j=0;j<4;j++)
                    acc[i][j] += am[i]*bn[j];
        }
        __syncthreads();
    }
    #pragma unroll
    for (int i=0;i<8;i++){
        int row = mbase + ty*8 + i;
        if (row >= M) continue;
        #pragma unroll
        for (int j=0;j<4;j++){
            int col = nbase + tx*4 + j;
            float v = acc[i][j];
            if (bias)   v += bias[col];
            if (useRes) v += g_x2[row*256 + col];
            C[(row*256 + col)*cstride] = v;
        }
    }
}

// ---------------------------------------------------------------------------
// causal attention per (b,h): S=64, D=64.
// ---------------------------------------------------------------------------
__global__ void attn_kernel(){
    __shared__ float smA[64*68];   // Q^T, then probs
    __shared__ float smB[64*68];   // K^T, then V
    int h = blockIdx.x, b = blockIdx.y;
    int t = threadIdx.x;
    const float* qb = g_q + (b*64)*256 + h*64;
    const float* kb = g_k + (b*64)*256 + h*64;
    const float* vb = g_v + (b*64)*256 + h*64;

    #pragma unroll
    for (int it = 0; it < 16; ++it){
        int idx = it*256 + t;
        int s = idx >> 6, d = idx & 63;
        smA[d*68 + s] = qb[s*256 + d];
        smB[d*68 + s] = kb[s*256 + d];
    }
    __syncthreads();

    int ib = t >> 4, jb = t & 15;
    float acc[4][4];
    #pragma unroll
    for (int r=0;r<4;r++)
        #pragma unroll
        for (int c=0;c<4;c++) acc[r][c]=0.f;

    for (int d = 0; d < 64; ++d){
        float4 qa = *(const float4*)&smA[d*68 + ib*4];
        float4 ka = *(const float4*)&smB[d*68 + jb*4];
        float qv[4] = {qa.x,qa.y,qa.z,qa.w};
        float kv[4] = {ka.x,ka.y,ka.z,ka.w};
        #pragma unroll
        for (int r=0;r<4;r++)
            #pragma unroll
            for (int c=0;c<4;c++)
                acc[r][c] += qv[r]*kv[c];
    }

    #pragma unroll
    for (int r=0;r<4;r++){
        int i = ib*4 + r;
        float m = -1e30f;
        #pragma unroll
        for (int c=0;c<4;c++){
            int j = jb*4 + c;
            float sc = (j <= i) ? acc[r][c]*0.125f : -1e30f;
            acc[r][c] = sc;
            m = fmaxf(m, sc);
        }
        #pragma unroll
        for (int off=1; off<16; off<<=1) m = fmaxf(m, __shfl_xor_sync(0xffffffffu, m, off));
        float sum = 0.f;
        #pragma unroll
        for (int c=0;c<4;c++){
            int j = jb*4 + c;
            float e = (j <= i) ? __expf(acc[r][c]-m) : 0.f;
            acc[r][c] = e; sum += e;
        }
        #pragma unroll
        for (int off=1; off<16; off<<=1) sum += __shfl_xor_sync(0xffffffffu, sum, off);
        float inv = 1.f/sum;
        #pragma unroll
        for (int c=0;c<4;c++) acc[r][c] *= inv;
    }
    __syncthreads();

    #pragma unroll
    for (int r=0;r<4;r++){
        float4 pv = make_float4(acc[r][0], acc[r][1], acc[r][2], acc[r][3]);
        *(float4*)&smA[(ib*4+r)*68 + jb*4] = pv;
    }
    #pragma unroll
    for (int it = 0; it < 16; ++it){
        int idx = it*256 + t;
        int s = idx >> 6, d = idx & 63;
        smB[s*68 + d] = vb[s*256 + d];
    }
    __syncthreads();

    float o[4][4];
    #pragma unroll
    for (int r=0;r<4;r++)
        #pragma unroll
        for (int c=0;c<4;c++) o[r][c]=0.f;

    for (int j = 0; j < 64; ++j){
        float4 va = *(const float4*)&smB[j*68 + jb*4];
        float vv[4] = {va.x,va.y,va.z,va.w};
        float pa[4];
        #pragma unroll
        for (int r=0;r<4;r++) pa[r] = smA[(ib*4+r)*68 + j];
        #pragma unroll
        for (int r=0;r<4;r++)
            #pragma unroll
            for (int c=0;c<4;c++)
                o[r][c] += pa[r]*vv[c];
    }
    float* ob = g_q + (b*64)*256 + h*64;
    #pragma unroll
    for (int r=0;r<4;r++){
        float4 ov = make_float4(o[r][0],o[r][1],o[r][2],o[r][3]);
        *(float4*)&ob[(ib*4+r)*256 + jb*4] = ov;
    }
}

// ---------------------------------------------------------------------------
// scatter-max pooling
// ---------------------------------------------------------------------------
__global__ void pool_kernel(){
    __shared__ int hs[64];
    int bx = blockIdx.x;
    int p = bx >> 6, n = bx & 63;
    int t = threadIdx.x;
    if (t < 64) hs[t] = g_hard[(p*64+n)*64 + t];
    __syncthreads();
    int b = n*16 + p;
    float a0=-3.402823466e38f, a1=a0, a2=a0, a3=a0;
    for (int s = 0; s < 64; ++s){
        float v = g_x2[(b*64+s)*256 + t];
        int ks = hs[s];
        a0 = fmaxf(a0, ks==0 ? v : 0.f);
        a1 = fmaxf(a1, ks==1 ? v : 0.f);
        a2 = fmaxf(a2, ks==2 ? v : 0.f);
        a3 = fmaxf(a3, ks==3 ? v : 0.f);
    }
    int base = (p*64+n)*1024 + t;
    g_clus[base      ] = a0;
    g_clus[base + 256] = a1;
    g_clus[base + 512] = a2;
    g_clus[base + 768] = a3;
}

// ---------------------------------------------------------------------------
extern "C" void kernel_launch(void* const* d_in, const int* in_sizes, int n_in,
                              void* d_out, int out_size){
    const float* x   = (const float*)d_in[0];
    const float* pro = (const float*)d_in[1];
    const float* Wq  = (const float*)d_in[2];
    const float* bq  = (const float*)d_in[3];
    const float* Wk  = (const float*)d_in[4];
    const float* bk  = (const float*)d_in[5];
    const float* Wv  = (const float*)d_in[6];
    const float* bv  = (const float*)d_in[7];
    const float* Wo  = (const float*)d_in[8];
    const float* bo  = (const float*)d_in[9];
    const float* fcb = (const float*)d_in[10];
    float* out = (float*)d_out;

    (void)in_sizes; (void)n_in; (void)out_size;

    cudaFuncSetAttribute(mgemm_kernel,
                         cudaFuncAttributeMaxDynamicSharedMemorySize, MG_SMEM);

    transpose_kernel<<<dim3(8,8,64),256>>>(x);
    cluster_kernel<<<1024,256>>>(x, pro);
    mode_kernel<<<16,256>>>(out + Nn*Cc*Pp);

    // pre-convert weights (transposed bf16 hi/lo)
    wconv_kernel<<<16,256>>>(Wq, 0);
    wconv_kernel<<<16,256>>>(Wk, 1);
    wconv_kernel<<<16,256>>>(Wv, 2);
    wconv_kernel<<<16,256>>>(Wo, 3);

    // QKV projections on pipelined HMMA
    mgemm_kernel<<<dim3(512,2),256,MG_SMEM>>>(0, 0, bq, 0, 1);
    mgemm_kernel<<<dim3(512,2),256,MG_SMEM>>>(0, 1, bk, 0, 2);
    mgemm_kernel<<<dim3(512,2),256,MG_SMEM>>>(0, 2, bv, 0, 3);

    attn_kernel<<<dim3(Hh,Bb),256>>>();

    // out-proj + bias + residual, in place into g_x2
    mgemm_kernel<<<dim3(512,2),256,MG_SMEM>>>(1, 3, bo, 1, 0);

    pool_kernel<<<1024,256>>>();
    sgemm_kernel<<<dim3(1,4,16),256>>>(4, fcb, nullptr, 0, 5, out, 16, 64, 1024, 1024, 1);
}

// round 17
// speedup vs baseline: 1.6230x; 1.1362x over previous
#include <cuda_runtime.h>
#include <cuda_bf16.h>

// Problem constants
#define Nn 64
#define Cc 256
#define Ss 64
#define Pp 16
#define Kk 4
#define Hh 4
#define Dd 64
#define Bb (Nn*Pp)      // 1024
#define MR (Bb*Ss)      // 65536 rows for the big GEMMs

// Scratch (device-static; no allocations allowed)
__device__ float g_x2 [MR*Cc];
__device__ float g_q  [MR*Cc];
__device__ float g_k  [MR*Cc];
__device__ float g_v  [MR*Cc];
__device__ float g_clus[Pp*Nn*Kk*Cc];
__device__ int   g_hard[Pp*Nn*Ss];
// pre-converted transposed weights: [slot][n*256+k], bf16 hi/lo
__device__ unsigned short g_wth[4*65536];
__device__ unsigned short g_wtl[4*65536];

// ---------------------------------------------------------------------------
// transpose: x (n,c,s,p) -> x2 (n*p, s, c)
// ---------------------------------------------------------------------------
__global__ void transpose_kernel(const float* __restrict__ x){
    __shared__ float tile[32][129];
    int n  = blockIdx.z;
    int c0 = blockIdx.x * 32;
    int sp0= blockIdx.y * 128;
    int t  = threadIdx.x;
    #pragma unroll
    for (int it = 0; it < 16; ++it){
        int idx = it*256 + t;
        int cl = idx >> 7, spl = idx & 127;
        tile[cl][spl] = x[(n*Cc + c0 + cl)*1024 + sp0 + spl];
    }
    __syncthreads();
    #pragma unroll
    for (int it = 0; it < 4; ++it){
        int spl = it*32 + (t >> 3);
        int cl  = (t & 7) * 4;
        int sp  = sp0 + spl;
        int s = sp >> 4, p = sp & 15;
        float4 v = make_float4(tile[cl][spl], tile[cl+1][spl],
                               tile[cl+2][spl], tile[cl+3][spl]);
        *(float4*)&g_x2[((n*Pp + p)*Ss + s)*Cc + c0 + cl] = v;
    }
}

// ---------------------------------------------------------------------------
// clustering
// ---------------------------------------------------------------------------
__global__ void cluster_kernel(const float* __restrict__ x,
                               const float* __restrict__ protos){
    __shared__ float mu[256], rs[256];
    __shared__ float pr[4][256];
    __shared__ float pn[4];
    int bx = blockIdx.x;
    int p = bx >> 6, n = bx & 63;
    int t = threadIdx.x;

    for (int i = t; i < 1024; i += 256) pr[i>>8][i&255] = protos[p*1024 + i];
    __syncthreads();
    if (t < 4){
        float s = 0.f;
        for (int c = 0; c < 256; ++c){ float v = pr[t][c]; s += v*v; }
        pn[t] = rsqrtf(s);
    }
    __syncthreads();
    for (int i = t; i < 1024; i += 256) pr[i>>8][i&255] *= pn[i>>8];

    {
        int c = t;
        const float* xp = x + (n*256 + c)*1024 + p;
        float s1 = 0.f, s2 = 0.f;
        for (int s = 0; s < 64; ++s){ float v = xp[s*16]; s1 += v; s2 += v*v; }
        float m = s1 * (1.f/64.f);
        float var = s2 * (1.f/64.f) - m*m;
        mu[c] = m; rs[c] = rsqrtf(var + 1e-5f);
    }
    __syncthreads();

    int s = t >> 2, q4 = t & 3;
    const float* xs = x + (n*256)*1024 + s*16 + p;
    float nr = 0.f, d0=0.f, d1=0.f, d2=0.f, d3=0.f;
    for (int cc = 0; cc < 64; ++cc){
        int c = cc*4 + q4;
        float v = (xs[c*1024] - mu[c]) * rs[c];
        nr += v*v;
        d0 += v*pr[0][c]; d1 += v*pr[1][c];
        d2 += v*pr[2][c]; d3 += v*pr[3][c];
    }
    #pragma unroll
    for (int off = 1; off < 4; off <<= 1){
        nr += __shfl_xor_sync(0xffffffffu, nr, off);
        d0 += __shfl_xor_sync(0xffffffffu, d0, off);
        d1 += __shfl_xor_sync(0xffffffffu, d1, off);
        d2 += __shfl_xor_sync(0xffffffffu, d2, off);
        d3 += __shfl_xor_sync(0xffffffffu, d3, off);
    }
    if (q4 == 0){
        float inv = rsqrtf(nr);
        float s0 = d0*inv, s1v = d1*inv, s2v = d2*inv, s3v = d3*inv;
        int best = 0; float bv = s0;
        if (s1v > bv){ bv = s1v; best = 1; }
        if (s2v > bv){ bv = s2v; best = 2; }
        if (s3v > bv){ bv = s3v; best = 3; }
        g_hard[(p*64 + n)*64 + s] = best;
    }
}

__global__ void mode_kernel(float* __restrict__ outTail){
    int t = blockIdx.x*256 + threadIdx.x;       // 4096 = n*s
    int n = t >> 6, s = t & 63;
    int cnt[4] = {0,0,0,0};
    #pragma unroll
    for (int p = 0; p < 16; ++p) cnt[g_hard[(p*64+n)*64 + s]]++;
    int best = 0, bv = cnt[0];
    if (cnt[1] > bv){ bv = cnt[1]; best = 1; }
    if (cnt[2] > bv){ bv = cnt[2]; best = 2; }
    if (cnt[3] > bv){ bv = cnt[3]; best = 3; }
    outTail[t] = (float)best;
}

// ---------------------------------------------------------------------------
__device__ __forceinline__ float* selbuf(int sel, float* ext){
    switch (sel){
        case 0: return g_x2;
        case 1: return g_q;
        case 2: return g_k;
        case 3: return g_v;
        case 4: return g_clus;
        default: return ext;
    }
}

__device__ __forceinline__ unsigned smem_u32(const void* p){
    unsigned a;
    asm("{ .reg .u64 t; cvta.to.shared.u64 t, %1; cvt.u32.u64 %0, t; }"
        : "=r"(a) : "l"(p));
    return a;
}
__device__ __forceinline__ void split2(float x, unsigned short& h, unsigned short& l){
    __nv_bfloat16 hb = __float2bfloat16(x);
    __nv_bfloat16 lb = __float2bfloat16(x - __bfloat162float(hb));
    h = __bfloat16_as_ushort(hb);
    l = __bfloat16_as_ushort(lb);
}
__device__ __forceinline__ void mma16816(float* c, const unsigned* a, const unsigned* b){
    asm volatile(
        "mma.sync.aligned.m16n8k16.row.col.f32.bf16.bf16.f32 "
        "{%0,%1,%2,%3}, {%4,%5,%6,%7}, {%8,%9}, {%0,%1,%2,%3};"
        : "+f"(c[0]), "+f"(c[1]), "+f"(c[2]), "+f"(c[3])
        : "r"(a[0]), "r"(a[1]), "r"(a[2]), "r"(a[3]),
          "r"(b[0]), "r"(b[1]));
}

// ---------------------------------------------------------------------------
// wconv4: all four W[k][n] fp32 -> g_wth/g_wtl[slot][n][k] bf16 hi/lo.
// grid (16, 4): blockIdx.y = slot.
// ---------------------------------------------------------------------------
__global__ void wconv4_kernel(const float* __restrict__ W0,
                              const float* __restrict__ W1,
                              const float* __restrict__ W2,
                              const float* __restrict__ W3){
    __shared__ unsigned short shh[64][65], shl[64][65];
    int slot = blockIdx.y;
    const float* W = (slot == 0) ? W0 : (slot == 1) ? W1 : (slot == 2) ? W2 : W3;
    int k0 = (blockIdx.x & 3) * 64;
    int n0 = (blockIdx.x >> 2) * 64;
    int t = threadIdx.x;
    #pragma unroll
    for (int it = 0; it < 16; ++it){
        int idx = it*256 + t;
        int kk = idx >> 6, nn = idx & 63;
        float v = W[(k0 + kk)*256 + n0 + nn];
        unsigned short h, l; split2(v, h, l);
        shh[nn][kk] = h; shl[nn][kk] = l;
    }
    __syncthreads();
    #pragma unroll
    for (int it = 0; it < 2; ++it){
        int idx = it*256 + t;          // 512 = 64 rows x 8 segs
        int row = idx >> 3, seg = idx & 7;
        unsigned short th[8], tl[8];
        #pragma unroll
        for (int e = 0; e < 8; ++e){
            th[e] = shh[row][seg*8 + e];
            tl[e] = shl[row][seg*8 + e];
        }
        int o = slot*65536 + (n0 + row)*256 + k0 + seg*8;
        *(uint4*)&g_wth[o] = *(uint4*)th;
        *(uint4*)&g_wtl[o] = *(uint4*)tl;
    }
}

// ===========================================================================
// mgemm: C(65536x256) = A * W [+bias][+res] — HMMA split-bf16, pipelined.
// CTA 128x128, 8 warps (2M x 4N), K chunks of 32, double-buffered dynamic smem.
// __launch_bounds__(256,2): cap regs at 128 so 2 CTAs co-reside per SM.
// ===========================================================================
#define AST 40
#define TILE_SH 5120
#define BUF_SH  20480
#define MG_SMEM (2*BUF_SH*2)   // 81920 bytes

__global__ void __launch_bounds__(256, 2) mgemm_kernel(
    int aSel, int wSlot, const float* __restrict__ bias, int useRes, int cSel)
{
    extern __shared__ unsigned short sm[];
    const float* A = selbuf(aSel, nullptr);
    float* C = selbuf(cSel, nullptr);
    const unsigned short* WH = g_wth + wSlot*65536;
    const unsigned short* WL = g_wtl + wSlot*65536;

    int t = threadIdx.x, w = t >> 5, lane = t & 31;
    int g = lane >> 2, q = lane & 3;
    int mb = blockIdx.x * 128, nb = blockIdx.y * 128;
    int Mw = (w & 1) * 64, Nw = (w >> 1) * 32;

    float acc[4][4][4];
    #pragma unroll
    for (int mf = 0; mf < 4; ++mf)
        #pragma unroll
        for (int nf = 0; nf < 4; ++nf)
            #pragma unroll
            for (int r = 0; r < 4; ++r) acc[mf][nf][r] = 0.f;

    float4 apf[4];

    auto issueB = [&](int kc, int buf){
        unsigned short* Bh = sm + buf*BUF_SH + 2*TILE_SH;
        unsigned short* Bl = sm + buf*BUF_SH + 3*TILE_SH;
        #pragma unroll
        for (int it = 0; it < 2; ++it){
            int idx = it*256 + t;
            int n = idx >> 2, seg = idx & 3;
            unsigned dh = smem_u32(&Bh[n*AST + seg*8]);
            unsigned dl = smem_u32(&Bl[n*AST + seg*8]);
            const unsigned short* sh = &WH[(nb + n)*256 + kc*32 + seg*8];
            const unsigned short* sl = &WL[(nb + n)*256 + kc*32 + seg*8];
            asm volatile("cp.async.ca.shared.global [%0], [%1], 16;" :: "r"(dh), "l"(sh));
            asm volatile("cp.async.ca.shared.global [%0], [%1], 16;" :: "r"(dl), "l"(sl));
        }
        asm volatile("cp.async.commit_group;" ::: "memory");
    };
    auto loadA = [&](int kc){
        #pragma unroll
        for (int it = 0; it < 4; ++it){
            int idx = it*256 + t;
            int row = idx >> 3, j4 = (idx & 7) * 4;
            apf[it] = *(const float4*)&A[(mb + row)*256 + kc*32 + j4];
        }
    };
    auto storeA = [&](int buf){
        unsigned short* Ah = sm + buf*BUF_SH;
        unsigned short* Al = sm + buf*BUF_SH + TILE_SH;
        #pragma unroll
        for (int it = 0; it < 4; ++it){
            int idx = it*256 + t;
            int row = idx >> 3, j4 = (idx & 7) * 4;
            float vv[4] = {apf[it].x, apf[it].y, apf[it].z, apf[it].w};
            unsigned long long ph = 0ull, pl = 0ull;
            #pragma unroll
            for (int e = 0; e < 4; ++e){
                unsigned short h, l; split2(vv[e], h, l);
                ph |= (unsigned long long)h << (16*e);
                pl |= (unsigned long long)l << (16*e);
            }
            *(unsigned long long*)&Ah[row*AST + j4] = ph;
            *(unsigned long long*)&Al[row*AST + j4] = pl;
        }
    };

    // prologue: fill buffer 0 with chunk 0
    loadA(0);
    storeA(0);
    issueB(0, 0);
    asm volatile("cp.async.wait_group 0;" ::: "memory");
    __syncthreads();

    #pragma unroll 1
    for (int kc = 0; kc < 8; ++kc){
        int buf = kc & 1;
        if (kc < 7){
            issueB(kc + 1, buf ^ 1);
            loadA(kc + 1);
        }
        {
            const unsigned short* Ah = sm + buf*BUF_SH;
            const unsigned short* Al = Ah + TILE_SH;
            const unsigned short* Bh = Ah + 2*TILE_SH;
            const unsigned short* Bl = Ah + 3*TILE_SH;
            #pragma unroll
            for (int ks = 0; ks < 2; ++ks){
                int k0 = ks*16 + q*2;
                unsigned bh[4][2], bl[4][2];
                #pragma unroll
                for (int nf = 0; nf < 4; ++nf){
                    int n = Nw + nf*8 + g;
                    bh[nf][0] = *(const unsigned*)&Bh[n*AST + k0];
                    bh[nf][1] = *(const unsigned*)&Bh[n*AST + k0 + 8];
                    bl[nf][0] = *(const unsigned*)&Bl[n*AST + k0];
                    bl[nf][1] = *(const unsigned*)&Bl[n*AST + k0 + 8];
                }
                #pragma unroll
                for (int mf = 0; mf < 4; ++mf){
                    int r0 = Mw + mf*16 + g;
                    unsigned ah[4], al[4];
                    ah[0] = *(const unsigned*)&Ah[(r0    )*AST + k0];
                    ah[1] = *(const unsigned*)&Ah[(r0 + 8)*AST + k0];
                    ah[2] = *(const unsigned*)&Ah[(r0    )*AST + k0 + 8];
                    ah[3] = *(const unsigned*)&Ah[(r0 + 8)*AST + k0 + 8];
                    al[0] = *(const unsigned*)&Al[(r0    )*AST + k0];
                    al[1] = *(const unsigned*)&Al[(r0 + 8)*AST + k0];
                    al[2] = *(const unsigned*)&Al[(r0    )*AST + k0 + 8];
                    al[3] = *(const unsigned*)&Al[(r0 + 8)*AST + k0 + 8];
                    #pragma unroll
                    for (int nf = 0; nf < 4; ++nf){
                        mma16816(acc[mf][nf], ah, bh[nf]);
                        mma16816(acc[mf][nf], ah, bl[nf]);
                        mma16816(acc[mf][nf], al, bh[nf]);
                    }
                }
            }
        }
        if (kc < 7){
            asm volatile("cp.async.wait_group 0;" ::: "memory");
            storeA(buf ^ 1);
        }
        __syncthreads();
    }

    // epilogue
    #pragma unroll
    for (int mf = 0; mf < 4; ++mf){
        int r0 = mb + Mw + mf*16 + g;
        #pragma unroll
        for (int nf = 0; nf < 4; ++nf){
            int c0i = nb + Nw + nf*8 + q*2;
            float b0 = 0.f, b1 = 0.f;
            if (bias){ b0 = bias[c0i]; b1 = bias[c0i+1]; }
            float v00 = acc[mf][nf][0] + b0, v01 = acc[mf][nf][1] + b1;
            float v10 = acc[mf][nf][2] + b0, v11 = acc[mf][nf][3] + b1;
            if (useRes){
                v00 += g_x2[r0*256 + c0i];     v01 += g_x2[r0*256 + c0i + 1];
                v10 += g_x2[(r0+8)*256 + c0i]; v11 += g_x2[(r0+8)*256 + c0i + 1];
            }
            *(float2*)&C[r0*256 + c0i]     = make_float2(v00, v01);
            *(float2*)&C[(r0+8)*256 + c0i] = make_float2(v10, v11);
        }
    }
}

// ---------------------------------------------------------------------------
// small SGEMM (kept for the per-part FC: M=64 needs the guards)
// ---------------------------------------------------------------------------
__global__ void sgemm_kernel(int aSel, const float* __restrict__ Bm,
                             const float* __restrict__ bias, int useRes,
                             int cSel, float* extC, int cstride,
                             int M, int K, int lda, int perp)
{
    __shared__ float As[16][132];
    __shared__ float Bs[16][64];
    const float* A = selbuf(aSel, nullptr);
    float* C = selbuf(cSel, extC);
    const float* Bp = Bm;
    if (perp){
        int z = blockIdx.z;
        A  += z * 64 * 1024;
        Bp += z * 1024 * 256;
        C  += z;
    }
    int mbase = blockIdx.x * 128;
    int nbase = blockIdx.y * 64;
    int t = threadIdx.x;
    int tx = t & 15, ty = t >> 4;

    float acc[8][4];
    #pragma unroll
    for (int i=0;i<8;i++)
        #pragma unroll
        for (int j=0;j<4;j++) acc[i][j]=0.f;

    int arow = t >> 1;
    int ak   = (t & 1) * 8;
    int brow = t >> 4;
    int bc   = (t & 15) * 4;

    int ktiles = K >> 4;
    for (int kt = 0; kt < ktiles; ++kt){
        float4 a0, a1;
        if (mbase + arow < M){
            const float* ap = A + (mbase + arow)*lda + kt*16 + ak;
            a0 = *(const float4*)ap;
            a1 = *(const float4*)(ap + 4);
        } else {
            a0 = make_float4(0.f,0.f,0.f,0.f); a1 = a0;
        }
        As[ak+0][arow]=a0.x; As[ak+1][arow]=a0.y; As[ak+2][arow]=a0.z; As[ak+3][arow]=a0.w;
        As[ak+4][arow]=a1.x; As[ak+5][arow]=a1.y; As[ak+6][arow]=a1.z; As[ak+7][arow]=a1.w;
        *(float4*)&Bs[brow][bc] = *(const float4*)&Bp[(kt*16 + brow)*256 + nbase + bc];
        __syncthreads();
        #pragma unroll
        for (int k = 0; k < 16; ++k){
            float4 a0v = *(const float4*)&As[k][ty*8];
            float4 a1v = *(const float4*)&As[k][ty*8+4];
            float4 bv  = *(const float4*)&Bs[k][tx*4];
            float am[8] = {a0v.x,a0v.y,a0v.z,a0v.w,a1v.x,a1v.y,a1v.z,a1v.w};
            float bn[4] = {bv.x,bv.y,bv.z,bv.w};
            #pragma unroll
            for (int i=0;i<8;i++)
                #pragma unroll
                for (int j=0;j<4;j++)
                    acc[i][j] += am[i]*bn[j];
        }
        __syncthreads();
    }
    #pragma unroll
    for (int i=0;i<8;i++){
        int row = mbase + ty*8 + i;
        if (row >= M) continue;
        #pragma unroll
        for (int j=0;j<4;j++){
            int col = nbase + tx*4 + j;
            float v = acc[i][j];
            if (bias)   v += bias[col];
            if (useRes) v += g_x2[row*256 + col];
            C[(row*256 + col)*cstride] = v;
        }
    }
}

// ---------------------------------------------------------------------------
// causal attention per (b,h): S=64, D=64.
// ---------------------------------------------------------------------------
__global__ void attn_kernel(){
    __shared__ float smA[64*68];   // Q^T, then probs
    __shared__ float smB[64*68];   // K^T, then V
    int h = blockIdx.x, b = blockIdx.y;
    int t = threadIdx.x;
    const float* qb = g_q + (b*64)*256 + h*64;
    const float* kb = g_k + (b*64)*256 + h*64;
    const float* vb = g_v + (b*64)*256 + h*64;

    #pragma unroll
    for (int it = 0; it < 16; ++it){
        int idx = it*256 + t;
        int s = idx >> 6, d = idx & 63;
        smA[d*68 + s] = qb[s*256 + d];
        smB[d*68 + s] = kb[s*256 + d];
    }
    __syncthreads();

    int ib = t >> 4, jb = t & 15;
    float acc[4][4];
    #pragma unroll
    for (int r=0;r<4;r++)
        #pragma unroll
        for (int c=0;c<4;c++) acc[r][c]=0.f;

    for (int d = 0; d < 64; ++d){
        float4 qa = *(const float4*)&smA[d*68 + ib*4];
        float4 ka = *(const float4*)&smB[d*68 + jb*4];
        float qv[4] = {qa.x,qa.y,qa.z,qa.w};
        float kv[4] = {ka.x,ka.y,ka.z,ka.w};
        #pragma unroll
        for (int r=0;r<4;r++)
            #pragma unroll
            for (int c=0;c<4;c++)
                acc[r][c] += qv[r]*kv[c];
    }

    #pragma unroll
    for (int r=0;r<4;r++){
        int i = ib*4 + r;
        float m = -1e30f;
        #pragma unroll
        for (int c=0;c<4;c++){
            int j = jb*4 + c;
            float sc = (j <= i) ? acc[r][c]*0.125f : -1e30f;
            acc[r][c] = sc;
            m = fmaxf(m, sc);
        }
        #pragma unroll
        for (int off=1; off<16; off<<=1) m = fmaxf(m, __shfl_xor_sync(0xffffffffu, m, off));
        float sum = 0.f;
        #pragma unroll
        for (int c=0;c<4;c++){
            int j = jb*4 + c;
            float e = (j <= i) ? __expf(acc[r][c]-m) : 0.f;
            acc[r][c] = e; sum += e;
        }
        #pragma unroll
        for (int off=1; off<16; off<<=1) sum += __shfl_xor_sync(0xffffffffu, sum, off);
        float inv = 1.f/sum;
        #pragma unroll
        for (int c=0;c<4;c++) acc[r][c] *= inv;
    }
    __syncthreads();

    #pragma unroll
    for (int r=0;r<4;r++){
        float4 pv = make_float4(acc[r][0], acc[r][1], acc[r][2], acc[r][3]);
        *(float4*)&smA[(ib*4+r)*68 + jb*4] = pv;
    }
    #pragma unroll
    for (int it = 0; it < 16; ++it){
        int idx = it*256 + t;
        int s = idx >> 6, d = idx & 63;
        smB[s*68 + d] = vb[s*256 + d];
    }
    __syncthreads();

    float o[4][4];
    #pragma unroll
    for (int r=0;r<4;r++)
        #pragma unroll
        for (int c=0;c<4;c++) o[r][c]=0.f;

    for (int j = 0; j < 64; ++j){
        float4 va = *(const float4*)&smB[j*68 + jb*4];
        float vv[4] = {va.x,va.y,va.z,va.w};
        float pa[4];
        #pragma unroll
        for (int r=0;r<4;r++) pa[r] = smA[(ib*4+r)*68 + j];
        #pragma unroll
        for (int r=0;r<4;r++)
            #pragma unroll
            for (int c=0;c<4;c++)
                o[r][c] += pa[r]*vv[c];
    }
    float* ob = g_q + (b*64)*256 + h*64;
    #pragma unroll
    for (int r=0;r<4;r++){
        float4 ov = make_float4(o[r][0],o[r][1],o[r][2],o[r][3]);
        *(float4*)&ob[(ib*4+r)*256 + jb*4] = ov;
    }
}

// ---------------------------------------------------------------------------
// scatter-max pooling
// ---------------------------------------------------------------------------
__global__ void pool_kernel(){
    __shared__ int hs[64];
    int bx = blockIdx.x;
    int p = bx >> 6, n = bx & 63;
    int t = threadIdx.x;
    if (t < 64) hs[t] = g_hard[(p*64+n)*64 + t];
    __syncthreads();
    int b = n*16 + p;
    float a0=-3.402823466e38f, a1=a0, a2=a0, a3=a0;
    for (int s = 0; s < 64; ++s){
        float v = g_x2[(b*64+s)*256 + t];
        int ks = hs[s];
        a0 = fmaxf(a0, ks==0 ? v : 0.f);
        a1 = fmaxf(a1, ks==1 ? v : 0.f);
        a2 = fmaxf(a2, ks==2 ? v : 0.f);
        a3 = fmaxf(a3, ks==3 ? v : 0.f);
    }
    int base = (p*64+n)*1024 + t;
    g_clus[base      ] = a0;
    g_clus[base + 256] = a1;
    g_clus[base + 512] = a2;
    g_clus[base + 768] = a3;
}

// ---------------------------------------------------------------------------
extern "C" void kernel_launch(void* const* d_in, const int* in_sizes, int n_in,
                              void* d_out, int out_size){
    const float* x   = (const float*)d_in[0];
    const float* pro = (const float*)d_in[1];
    const float* Wq  = (const float*)d_in[2];
    const float* bq  = (const float*)d_in[3];
    const float* Wk  = (const float*)d_in[4];
    const float* bk  = (const float*)d_in[5];
    const float* Wv  = (const float*)d_in[6];
    const float* bv  = (const float*)d_in[7];
    const float* Wo  = (const float*)d_in[8];
    const float* bo  = (const float*)d_in[9];
    const float* fcb = (const float*)d_in[10];
    float* out = (float*)d_out;

    (void)in_sizes; (void)n_in; (void)out_size;

    cudaFuncSetAttribute(mgemm_kernel,
                         cudaFuncAttributeMaxDynamicSharedMemorySize, MG_SMEM);

    transpose_kernel<<<dim3(8,8,64),256>>>(x);
    cluster_kernel<<<1024,256>>>(x, pro);
    mode_kernel<<<16,256>>>(out + Nn*Cc*Pp);

    // pre-convert all weights (one launch)
    wconv4_kernel<<<dim3(16,4),256>>>(Wq, Wk, Wv, Wo);

    // QKV projections on pipelined HMMA (2 CTA/SM)
    mgemm_kernel<<<dim3(512,2),256,MG_SMEM>>>(0, 0, bq, 0, 1);
    mgemm_kernel<<<dim3(512,2),256,MG_SMEM>>>(0, 1, bk, 0, 2);
    mgemm_kernel<<<dim3(512,2),256,MG_SMEM>>>(0, 2, bv, 0, 3);

    attn_kernel<<<dim3(Hh,Bb),256>>>();

    // out-proj + bias + residual, in place into g_x2
    mgemm_kernel<<<dim3(512,2),256,MG_SMEM>>>(1, 3, bo, 1, 0);

    pool_kernel<<<1024,256>>>();
    sgemm_kernel<<<dim3(1,4,16),256>>>(4, fcb, nullptr, 0, 5, out, 16, 64, 1024, 1024, 1);
}